// round 12
// baseline (speedup 1.0000x reference)
#include <cuda_runtime.h>
#include <cuda_bf16.h>
#include <mma.h>
#include <cstdint>

using namespace nvcuda;

#define BATCH 16
#define DMODEL 1024
#define DM2 512
#define LSZ 4096
#define SS 64

// ---- scratch (device globals; no allocations allowed) ----
__device__ float g_bcdt[BATCH * SS * LSZ];                 // 16 MB fp32
__device__ __nv_bfloat16 g_conv_hi[BATCH * SS * LSZ];      // 8 MB
__device__ __nv_bfloat16 g_conv_lo[BATCH * SS * LSZ];
__device__ __nv_bfloat16 g_AB_hi[BATCH * SS * LSZ];
__device__ __nv_bfloat16 g_AB_lo[BATCH * SS * LSZ];
__device__ __nv_bfloat16 g_w_hi[SS * DM2];
__device__ __nv_bfloat16 g_w_lo[SS * DM2];
__device__ float g_ypre[BATCH * DM2 * LSZ];                // 128 MB

__device__ __forceinline__ uint32_t pk(__nv_bfloat16 a, __nv_bfloat16 b) {
    __nv_bfloat162 t; t.x = a; t.y = b;
    return *reinterpret_cast<uint32_t*>(&t);
}
__device__ __forceinline__ void split1(float v, __nv_bfloat16& hi, __nv_bfloat16& lo) {
    hi = __float2bfloat16_rn(v);
    lo = __float2bfloat16_rn(v - __bfloat162float(hi));
}
__device__ __forceinline__ void split4(float4 v, uint2& hv, uint2& lv) {
    __nv_bfloat16 h0, l0, h1, l1, h2, l2, h3, l3;
    split1(v.x, h0, l0); split1(v.y, h1, l1);
    split1(v.z, h2, l2); split1(v.w, h3, l3);
    hv = make_uint2(pk(h0, h1), pk(h2, h3));
    lv = make_uint2(pk(l0, l1), pk(l2, l3));
}

// shared tile geometry for all small-tile GEMMs: 64x64, ld 72, hi/lo pairs
#define T_LD 72
#define T_BYTES (64 * T_LD * 2)            // 9216
#define OFF_AHI 0
#define OFF_ALO T_BYTES
#define OFF_BHI (2 * T_BYTES)
#define OFF_BLO (3 * T_BYTES)
#define T_SMEM (4 * T_BYTES)               // 36864

// ============================================================
// k0w: w_bcdt -> bf16 hi/lo (tiny)
// ============================================================
__global__ void k0_convert_w(const float4* __restrict__ w4) {
    int tid = threadIdx.x;
#pragma unroll
    for (int k = 0; k < 4; k++) {
        int g = blockIdx.x * 1024 + k * 256 + tid;
        uint2 hv, lv;
        split4(w4[g], hv, lv);
        *reinterpret_cast<uint2*>(&g_w_hi[g * 4]) = hv;
        *reinterpret_cast<uint2*>(&g_w_lo[g * 4]) = lv;
    }
}

// ============================================================
// k1 (wmma small-tile): BCdt[s,l] = sum_d w[s,d]*xh[d,l] + bias
// block 64s x 64l, K=512 in 8 chunks. grid (64 l0, 16 b).
// ============================================================
__global__ void __launch_bounds__(256, 3)
k1_wmma(const float4* __restrict__ x4, const float* __restrict__ bias) {
    extern __shared__ __align__(16) char smem[];
    __nv_bfloat16* Whi = reinterpret_cast<__nv_bfloat16*>(smem + OFF_AHI);
    __nv_bfloat16* Wlo = reinterpret_cast<__nv_bfloat16*>(smem + OFF_ALO);
    __nv_bfloat16* Xhi = reinterpret_cast<__nv_bfloat16*>(smem + OFF_BHI);
    __nv_bfloat16* Xlo = reinterpret_cast<__nv_bfloat16*>(smem + OFF_BLO);
    int b = blockIdx.y;
    int l0 = blockIdx.x * 64;
    int tid = threadIdx.x;
    int wid = tid >> 5;
    int wm = (wid >> 1) * 16;    // s
    int wn = (wid & 1) * 32;     // l

    wmma::fragment<wmma::accumulator, 16, 16, 16, float> acc[2];
#pragma unroll
    for (int j = 0; j < 2; j++) wmma::fill_fragment(acc[j], 0.f);

    for (int kc = 0; kc < DM2; kc += 64) {
#pragma unroll
        for (int k = 0; k < 4; k++) {            // W: 64s x 64k (hi+lo)
            int e = tid + k * 256;
            int s = e >> 4, q = e & 15;
            *reinterpret_cast<uint2*>(&Whi[s * T_LD + q * 4]) =
                *reinterpret_cast<const uint2*>(&g_w_hi[s * DM2 + kc + q * 4]);
            *reinterpret_cast<uint2*>(&Wlo[s * T_LD + q * 4]) =
                *reinterpret_cast<const uint2*>(&g_w_lo[s * DM2 + kc + q * 4]);
        }
#pragma unroll
        for (int k = 0; k < 4; k++) {            // X: 64k x 64l from fp32 x
            int e = tid + k * 256;
            int r = e >> 4, q = e & 15;
            float4 v = x4[((size_t)b * DMODEL + kc + r) * 1024 + (l0 >> 2) + q];
            uint2 hv, lv;
            split4(v, hv, lv);
            *reinterpret_cast<uint2*>(&Xhi[r * T_LD + q * 4]) = hv;
            *reinterpret_cast<uint2*>(&Xlo[r * T_LD + q * 4]) = lv;
        }
        __syncthreads();
#pragma unroll
        for (int ks = 0; ks < 4; ks++) {
            int kk = ks * 16;
            wmma::fragment<wmma::matrix_a, 16, 16, 16, __nv_bfloat16, wmma::row_major> ah, al;
            wmma::load_matrix_sync(ah, Whi + wm * T_LD + kk, T_LD);
            wmma::load_matrix_sync(al, Wlo + wm * T_LD + kk, T_LD);
#pragma unroll
            for (int j = 0; j < 2; j++) {
                wmma::fragment<wmma::matrix_b, 16, 16, 16, __nv_bfloat16, wmma::row_major> bh, bl;
                wmma::load_matrix_sync(bh, Xhi + kk * T_LD + wn + j * 16, T_LD);
                wmma::load_matrix_sync(bl, Xlo + kk * T_LD + wn + j * 16, T_LD);
                wmma::mma_sync(acc[j], ah, bh, acc[j]);
                wmma::mma_sync(acc[j], ah, bl, acc[j]);
                wmma::mma_sync(acc[j], al, bh, acc[j]);
            }
        }
        __syncthreads();
    }
    float* stage = reinterpret_cast<float*>(smem);          // [64][72] fp32
#pragma unroll
    for (int j = 0; j < 2; j++)
        wmma::store_matrix_sync(stage + wm * T_LD + wn + j * 16, acc[j],
                                T_LD, wmma::mem_row_major);
    __syncthreads();
#pragma unroll
    for (int k = 0; k < 4; k++) {
        int g = tid + k * 256;               // 1024 f4 = 64 rows x 16
        int row = g >> 4, c4 = g & 15;
        float bv = bias[row];
        float4 v = *reinterpret_cast<const float4*>(&stage[row * T_LD + c4 * 4]);
        v.x += bv; v.y += bv; v.z += bv; v.w += bv;
        *reinterpret_cast<float4*>(
            &g_bcdt[((size_t)b * SS + row) * LSZ + l0 + c4 * 4]) = v;
    }
}

// ============================================================
// k2: conv3x3 + softmax; writes bf16 hi/lo of conv and AB.
// ============================================================
__global__ void k2_conv_softmax(const float* __restrict__ wdw,
                                const float* __restrict__ bdw,
                                const float* __restrict__ A,
                                const float* __restrict__ coeffs) {
    __shared__ float sm[66][68];
    __shared__ float red[8];
    int s = blockIdx.x, b = blockIdx.y;
    int tid = threadIdx.x;
    size_t off = ((size_t)b * SS + s) * LSZ;
    const float* plane = g_bcdt + off;

    for (int e = tid; e < 66 * 68; e += 256) ((float*)sm)[e] = 0.f;
    __syncthreads();
#pragma unroll
    for (int k = 0; k < 16; k++) {
        int idx = tid + k * 256;
        sm[(idx >> 6) + 1][(idx & 63) + 1] = plane[idx];
    }
    __syncthreads();

    float w[9];
#pragma unroll
    for (int i = 0; i < 9; i++) w[i] = wdw[s * 9 + i];
    float bb = bdw[s];
    float c0 = coeffs[0], c2 = coeffs[2];
    float Av = A[s];

    float v[16];
    float lmax = -1e30f;
#pragma unroll
    for (int k = 0; k < 8; k++) {
        int base = tid * 2 + k * 512;
        int r = base >> 6, c = base & 63;
        float a0 = bb, a1 = bb;
#pragma unroll
        for (int i = 0; i < 3; i++)
#pragma unroll
            for (int j = 0; j < 3; j++) {
                float wv = w[i * 3 + j];
                a0 += wv * sm[r + i][c + j];
                a1 += wv * sm[r + i][c + 1 + j];
            }
        v[2 * k] = a0; v[2 * k + 1] = a1;
        lmax = fmaxf(lmax, fmaxf(c2 * a0, c2 * a1) + Av);
    }
#pragma unroll
    for (int o = 16; o > 0; o >>= 1)
        lmax = fmaxf(lmax, __shfl_xor_sync(0xffffffffu, lmax, o));
    if ((tid & 31) == 0) red[tid >> 5] = lmax;
    __syncthreads();
    float bmax = red[0];
#pragma unroll
    for (int i = 1; i < 8; i++) bmax = fmaxf(bmax, red[i]);
    __syncthreads();

    float ev[16];
    float lsum = 0.f;
#pragma unroll
    for (int k = 0; k < 16; k++) {
        ev[k] = __expf(c2 * v[k] + Av - bmax);
        lsum += ev[k];
    }
#pragma unroll
    for (int o = 16; o > 0; o >>= 1)
        lsum += __shfl_xor_sync(0xffffffffu, lsum, o);
    if ((tid & 31) == 0) red[tid >> 5] = lsum;
    __syncthreads();
    float bsum = 0.f;
#pragma unroll
    for (int i = 0; i < 8; i++) bsum += red[i];
    float inv = 1.f / bsum;

#pragma unroll
    for (int k = 0; k < 8; k++) {
        int base = tid * 2 + k * 512;
        float v0 = v[2 * k], v1 = v[2 * k + 1];
        __nv_bfloat16 ch0, cl0, ch1, cl1;
        split1(v0, ch0, cl0); split1(v1, ch1, cl1);
        *reinterpret_cast<uint32_t*>(&g_conv_hi[off + base]) = pk(ch0, ch1);
        *reinterpret_cast<uint32_t*>(&g_conv_lo[off + base]) = pk(cl0, cl1);
        float a0 = ev[2 * k] * inv * c0 * v0;
        float a1 = ev[2 * k + 1] * inv * c0 * v1;
        __nv_bfloat16 ah0, al0, ah1, al1;
        split1(a0, ah0, al0); split1(a1, ah1, al1);
        *reinterpret_cast<uint32_t*>(&g_AB_hi[off + base]) = pk(ah0, ah1);
        *reinterpret_cast<uint32_t*>(&g_AB_lo[off + base]) = pk(al0, al1);
    }
}

// ============================================================
// k3 (wmma small-tile): h[d,s] = sum_l xh[d,l]*AB[s,l]
// block 64d x 64s, L-split 8 (512 l in 8 chunks of 64). atomics.
// grid (8 lp, 8 dchunk, 16 b).
// ============================================================
__global__ void __launch_bounds__(256, 3)
k3_wmma(const float4* __restrict__ x4, float* __restrict__ hout) {
    extern __shared__ __align__(16) char smem[];
    __nv_bfloat16* Ahi = reinterpret_cast<__nv_bfloat16*>(smem + OFF_AHI);
    __nv_bfloat16* Alo = reinterpret_cast<__nv_bfloat16*>(smem + OFF_ALO);
    __nv_bfloat16* Bhi = reinterpret_cast<__nv_bfloat16*>(smem + OFF_BHI);
    __nv_bfloat16* Blo = reinterpret_cast<__nv_bfloat16*>(smem + OFF_BLO);
    int lp = blockIdx.x;                 // 0..7
    int d0 = blockIdx.y * 64;
    int b = blockIdx.z;
    int tid = threadIdx.x;
    int wid = tid >> 5;
    int wm = (wid >> 1) * 16;            // d
    int wn = (wid & 1) * 32;             // s

    wmma::fragment<wmma::accumulator, 16, 16, 16, float> acc[2];
#pragma unroll
    for (int j = 0; j < 2; j++) wmma::fill_fragment(acc[j], 0.f);

    for (int lc = 0; lc < 512; lc += 64) {
        int lbase = lp * 512 + lc;
#pragma unroll
        for (int k = 0; k < 4; k++) {        // A: 64d x 64l from fp32 x
            int e = tid + k * 256;
            int d = e >> 4, q = e & 15;
            float4 v = x4[((size_t)b * DMODEL + d0 + d) * 1024 + (lbase >> 2) + q];
            uint2 hv, lv;
            split4(v, hv, lv);
            *reinterpret_cast<uint2*>(&Ahi[d * T_LD + q * 4]) = hv;
            *reinterpret_cast<uint2*>(&Alo[d * T_LD + q * 4]) = lv;
        }
#pragma unroll
        for (int k = 0; k < 4; k++) {        // B: 64s x 64l (hi+lo)
            int e = tid + k * 256;
            int si = e >> 4, q = e & 15;
            size_t src = (((size_t)b * SS + si) << 12) + lbase + q * 4;
            *reinterpret_cast<uint2*>(&Bhi[si * T_LD + q * 4]) =
                *reinterpret_cast<const uint2*>(&g_AB_hi[src]);
            *reinterpret_cast<uint2*>(&Blo[si * T_LD + q * 4]) =
                *reinterpret_cast<const uint2*>(&g_AB_lo[src]);
        }
        __syncthreads();
#pragma unroll
        for (int ks = 0; ks < 4; ks++) {
            int kk = ks * 16;
            wmma::fragment<wmma::matrix_a, 16, 16, 16, __nv_bfloat16, wmma::row_major> ah, al;
            wmma::load_matrix_sync(ah, Ahi + wm * T_LD + kk, T_LD);
            wmma::load_matrix_sync(al, Alo + wm * T_LD + kk, T_LD);
#pragma unroll
            for (int j = 0; j < 2; j++) {
                wmma::fragment<wmma::matrix_b, 16, 16, 16, __nv_bfloat16, wmma::col_major> bh, bl;
                wmma::load_matrix_sync(bh, Bhi + (wn + j * 16) * T_LD + kk, T_LD);
                wmma::load_matrix_sync(bl, Blo + (wn + j * 16) * T_LD + kk, T_LD);
                wmma::mma_sync(acc[j], ah, bh, acc[j]);
                wmma::mma_sync(acc[j], ah, bl, acc[j]);
                wmma::mma_sync(acc[j], al, bh, acc[j]);
            }
        }
        __syncthreads();
    }
    float* stage = reinterpret_cast<float*>(smem);          // [64][72] fp32
#pragma unroll
    for (int j = 0; j < 2; j++)
        wmma::store_matrix_sync(stage + wm * T_LD + wn + j * 16, acc[j],
                                T_LD, wmma::mem_row_major);
    __syncthreads();
    float* hb = hout + ((size_t)b * DM2 + d0) * SS;
#pragma unroll
    for (int k = 0; k < 16; k++) {
        int e = tid + k * 256;               // 4096 = 64d x 64s
        int d = e >> 6, si = e & 63;
        atomicAdd(&hb[d * SS + si], stage[d * T_LD + si]);
    }
}

// ============================================================
// k4a (wmma small-tile): y_pre[d,l] = sum_s (c1*h)[d,s]*conv[s,l]
// block 64d x 64l, K=64. grid (64 l0, 8 dchunk, 16 b).
// ============================================================
__global__ void __launch_bounds__(256, 3)
k4a_wmma(const float4* __restrict__ h4, const float* __restrict__ coeffs) {
    extern __shared__ __align__(16) char smem[];
    __nv_bfloat16* Ahi = reinterpret_cast<__nv_bfloat16*>(smem + OFF_AHI);
    __nv_bfloat16* Alo = reinterpret_cast<__nv_bfloat16*>(smem + OFF_ALO);
    __nv_bfloat16* Bhi = reinterpret_cast<__nv_bfloat16*>(smem + OFF_BHI);
    __nv_bfloat16* Blo = reinterpret_cast<__nv_bfloat16*>(smem + OFF_BLO);
    int l0 = blockIdx.x * 64;
    int d0 = blockIdx.y * 64;
    int b = blockIdx.z;
    int tid = threadIdx.x;
    int wid = tid >> 5;
    int wm = (wid >> 1) * 16;            // d
    int wn = (wid & 1) * 32;             // l
    float c1 = coeffs[1];

    // A: h tile 64d x 64s, fp32 -> c1 -> split (1024 f4)
    const float4* hb4 = h4 + (((size_t)b * DM2 + d0) * SS >> 2);
#pragma unroll
    for (int k = 0; k < 4; k++) {
        int e = tid + k * 256;
        int d = e >> 4, q = e & 15;
        float4 v = hb4[e];
        v.x *= c1; v.y *= c1; v.z *= c1; v.w *= c1;
        uint2 hv, lv;
        split4(v, hv, lv);
        *reinterpret_cast<uint2*>(&Ahi[d * T_LD + q * 4]) = hv;
        *reinterpret_cast<uint2*>(&Alo[d * T_LD + q * 4]) = lv;
    }
#pragma unroll
    for (int k = 0; k < 4; k++) {            // B: conv 64s x 64l
        int e = tid + k * 256;
        int si = e >> 4, q = e & 15;
        size_t src = (((size_t)b * SS + si) << 12) + l0 + q * 4;
        *reinterpret_cast<uint2*>(&Bhi[si * T_LD + q * 4]) =
            *reinterpret_cast<const uint2*>(&g_conv_hi[src]);
        *reinterpret_cast<uint2*>(&Blo[si * T_LD + q * 4]) =
            *reinterpret_cast<const uint2*>(&g_conv_lo[src]);
    }
    __syncthreads();

    wmma::fragment<wmma::accumulator, 16, 16, 16, float> acc[2];
#pragma unroll
    for (int j = 0; j < 2; j++) wmma::fill_fragment(acc[j], 0.f);

#pragma unroll
    for (int ks = 0; ks < 4; ks++) {
        int kk = ks * 16;
        wmma::fragment<wmma::matrix_a, 16, 16, 16, __nv_bfloat16, wmma::row_major> ah, al;
        wmma::load_matrix_sync(ah, Ahi + wm * T_LD + kk, T_LD);
        wmma::load_matrix_sync(al, Alo + wm * T_LD + kk, T_LD);
#pragma unroll
        for (int j = 0; j < 2; j++) {
            wmma::fragment<wmma::matrix_b, 16, 16, 16, __nv_bfloat16, wmma::row_major> bh, bl;
            wmma::load_matrix_sync(bh, Bhi + kk * T_LD + wn + j * 16, T_LD);
            wmma::load_matrix_sync(bl, Blo + kk * T_LD + wn + j * 16, T_LD);
            wmma::mma_sync(acc[j], ah, bh, acc[j]);
            wmma::mma_sync(acc[j], ah, bl, acc[j]);
            wmma::mma_sync(acc[j], al, bh, acc[j]);
        }
    }
    __syncthreads();
    float* stage = reinterpret_cast<float*>(smem);          // [64][72] fp32
#pragma unroll
    for (int j = 0; j < 2; j++)
        wmma::store_matrix_sync(stage + wm * T_LD + wn + j * 16, acc[j],
                                T_LD, wmma::mem_row_major);
    __syncthreads();
#pragma unroll
    for (int k = 0; k < 4; k++) {
        int g = tid + k * 256;               // 1024 f4 = 64 rows x 16
        int row = g >> 4, c4 = g & 15;
        float4 v = *reinterpret_cast<const float4*>(&stage[row * T_LD + c4 * 4]);
        *reinterpret_cast<float4*>(
            &g_ypre[((size_t)b * DM2 + d0 + row) * LSZ + l0 + c4 * 4]) = v;
    }
}

// ============================================================
// k4b: final depthwise conv, float4 I/O, all 1024 channels.
// ============================================================
__global__ void k4b_conv(const float* __restrict__ x,
                         const float* __restrict__ wDW,
                         const float* __restrict__ bDW,
                         float* __restrict__ out) {
    __shared__ __align__(16) float sm[66][72];
    int c = blockIdx.x, b = blockIdx.y;
    int tid = threadIdx.x;
    const float* plane = (c < DM2)
        ? (g_ypre + ((size_t)b * DM2 + c) * LSZ)
        : (x + ((size_t)b * DMODEL + c) * LSZ);
    const float4* plane4 = reinterpret_cast<const float4*>(plane);

    if (tid < 72) { sm[0][tid] = 0.f; sm[65][tid] = 0.f; }
    else if (tid < 136) { int r = tid - 72 + 1; sm[r][3] = 0.f; sm[r][68] = 0.f; }
#pragma unroll
    for (int k = 0; k < 4; k++) {
        int g = tid + k * 256;
        int row = g >> 4, cq = g & 15;
        *reinterpret_cast<float4*>(&sm[row + 1][4 + cq * 4]) = plane4[g];
    }
    __syncthreads();

    float w[9];
#pragma unroll
    for (int i = 0; i < 9; i++) w[i] = wDW[c * 9 + i];
    float bb = bDW[c];
    float4* ob4 = reinterpret_cast<float4*>(out + ((size_t)b * DMODEL + c) * LSZ);
#pragma unroll
    for (int k = 0; k < 4; k++) {
        int g = tid + k * 256;
        int row = g >> 4, c0 = (g & 15) * 4;
        float o[4];
#pragma unroll
        for (int u = 0; u < 4; u++) {
            int cc = c0 + u;
            float acc = bb;
#pragma unroll
            for (int i = 0; i < 3; i++)
#pragma unroll
                for (int j = 0; j < 3; j++)
                    acc += w[i * 3 + j] * sm[row + i][3 + cc + j];
            o[u] = acc;
        }
        ob4[g] = make_float4(o[0], o[1], o[2], o[3]);
    }
}

// ============================================================
extern "C" void kernel_launch(void* const* d_in, const int* in_sizes, int n_in,
                              void* d_out, int out_size) {
    const float* x      = (const float*)d_in[0];
    const float* w_bcdt = (const float*)d_in[1];
    const float* b_bcdt = (const float*)d_in[2];
    const float* w_dw   = (const float*)d_in[3];
    const float* b_dw   = (const float*)d_in[4];
    const float* A      = (const float*)d_in[5];
    const float* coeffs = (const float*)d_in[6];
    const float* w_DW   = (const float*)d_in[7];
    const float* b_DW   = (const float*)d_in[8];

    float* y_out = (float*)d_out;                          // (16,1024,4096)
    float* h_out = y_out + (size_t)BATCH * DMODEL * LSZ;   // (16,512,64)

    cudaMemsetAsync(h_out, 0, (size_t)BATCH * DM2 * SS * sizeof(float));

    k0_convert_w<<<8, 256>>>((const float4*)w_bcdt);
    k1_wmma<<<dim3(64, 16), 256, T_SMEM>>>((const float4*)x, b_bcdt);
    k2_conv_softmax<<<dim3(64, 16), 256>>>(w_dw, b_dw, A, coeffs);
    k3_wmma<<<dim3(8, 8, 16), 256, T_SMEM>>>((const float4*)x, h_out);
    k4a_wmma<<<dim3(64, 8, 16), 256, T_SMEM>>>((const float4*)h_out, coeffs);
    k4b_conv<<<dim3(1024, 16), 256>>>(x, w_DW, b_DW, y_out);
}

// round 13
// speedup vs baseline: 1.0378x; 1.0378x over previous
#include <cuda_runtime.h>
#include <cuda_bf16.h>
#include <mma.h>
#include <cstdint>

using namespace nvcuda;

#define BATCH 16
#define DMODEL 1024
#define DM2 512
#define LSZ 4096
#define SS 64

// ---- scratch (device globals; no allocations allowed) ----
__device__ float g_bcdt[BATCH * SS * LSZ];                 // 16 MB fp32
__device__ __nv_bfloat16 g_conv_hi[BATCH * SS * LSZ];      // 8 MB
__device__ __nv_bfloat16 g_conv_lo[BATCH * SS * LSZ];
__device__ __nv_bfloat16 g_AB_hi[BATCH * SS * LSZ];
__device__ __nv_bfloat16 g_AB_lo[BATCH * SS * LSZ];
__device__ __nv_bfloat16 g_w_hi[SS * DM2];
__device__ __nv_bfloat16 g_w_lo[SS * DM2];
__device__ float g_ypre[BATCH * DM2 * LSZ];                // 128 MB

__device__ __forceinline__ uint32_t pk(__nv_bfloat16 a, __nv_bfloat16 b) {
    __nv_bfloat162 t; t.x = a; t.y = b;
    return *reinterpret_cast<uint32_t*>(&t);
}
__device__ __forceinline__ void split1(float v, __nv_bfloat16& hi, __nv_bfloat16& lo) {
    hi = __float2bfloat16_rn(v);
    lo = __float2bfloat16_rn(v - __bfloat162float(hi));
}
__device__ __forceinline__ void split4(float4 v, uint2& hv, uint2& lv) {
    __nv_bfloat16 h0, l0, h1, l1, h2, l2, h3, l3;
    split1(v.x, h0, l0); split1(v.y, h1, l1);
    split1(v.z, h2, l2); split1(v.w, h3, l3);
    hv = make_uint2(pk(h0, h1), pk(h2, h3));
    lv = make_uint2(pk(l0, l1), pk(l2, l3));
}
__device__ __forceinline__ uint32_t smem_u32(const void* p) {
    uint32_t a;
    asm("{ .reg .u64 t; cvta.to.shared.u64 t, %1; cvt.u32.u64 %0, t; }" : "=r"(a) : "l"(p));
    return a;
}
__device__ __forceinline__ void cp16(uint32_t dst, const void* src) {
    asm volatile("cp.async.cg.shared.global [%0], [%1], 16;" :: "r"(dst), "l"(src));
}
#define CP_COMMIT() asm volatile("cp.async.commit_group;" ::: "memory")
#define CP_WAIT1() asm volatile("cp.async.wait_group 1;" ::: "memory")
#define CP_WAIT0() asm volatile("cp.async.wait_group 0;" ::: "memory")

// ============================================================
// k0w: w_bcdt -> bf16 hi/lo (tiny)
// ============================================================
__global__ void k0_convert_w(const float4* __restrict__ w4) {
    int tid = threadIdx.x;
#pragma unroll
    for (int k = 0; k < 4; k++) {
        int g = blockIdx.x * 1024 + k * 256 + tid;
        uint2 hv, lv;
        split4(w4[g], hv, lv);
        *reinterpret_cast<uint2*>(&g_w_hi[g * 4]) = hv;
        *reinterpret_cast<uint2*>(&g_w_lo[g * 4]) = lv;
    }
}

// ============================================================
// k1 (wmma + cp.async W double-buffer):
// BCdt[s,l] = sum_d w[s,d]*xh[d,l] + bias[s]
// block 64s x 128l, K=512 in 8 chunks of 64.
// smem: W0hi W0lo W1hi W1lo (4x9216) | Xhi Xlo (2x17408) = 71680
// ============================================================
#define K1_WSZ 9216
#define K1_XLD 136
#define K1_X_HI 36864
#define K1_X_LO 54272
#define K1_SMEM 71680
#define K1_WLD 72

__global__ void k1_wmma(const float4* __restrict__ x4, const float* __restrict__ bias) {
    extern __shared__ __align__(16) char smem[];
    uint32_t sb = smem_u32(smem);
    __nv_bfloat16* Xhi = reinterpret_cast<__nv_bfloat16*>(smem + K1_X_HI);
    __nv_bfloat16* Xlo = reinterpret_cast<__nv_bfloat16*>(smem + K1_X_LO);
    int b = blockIdx.y;
    int l0 = blockIdx.x * 128;
    int tid = threadIdx.x;
    int wid = tid >> 5;
    int wm = (wid >> 1) * 16;    // s
    int wn = (wid & 1) * 64;     // l

    wmma::fragment<wmma::accumulator, 16, 16, 16, float> acc[4];
#pragma unroll
    for (int j = 0; j < 4; j++) wmma::fill_fragment(acc[j], 0.f);

    // issue W chunk 0 -> buf 0
    {
        int kc = 0;
#pragma unroll
        for (int k = 0; k < 2; k++) {
            int e = tid + k * 256;           // 512: s = e>>3, q = e&7
            int s = e >> 3, q = e & 7;
            cp16(sb + 0 * 18432 + s * (K1_WLD * 2) + q * 16,
                 &g_w_hi[s * DM2 + kc + q * 8]);
            cp16(sb + 0 * 18432 + K1_WSZ + s * (K1_WLD * 2) + q * 16,
                 &g_w_lo[s * DM2 + kc + q * 8]);
        }
        CP_COMMIT();
    }

    for (int it = 0; it < 8; it++) {
        int kc = it * 64;
        int cur = it & 1;
        if (it < 7) {                        // prefetch W chunk it+1 -> buf cur^1
            int kn = kc + 64;
#pragma unroll
            for (int k = 0; k < 2; k++) {
                int e = tid + k * 256;
                int s = e >> 3, q = e & 7;
                cp16(sb + (cur ^ 1) * 18432 + s * (K1_WLD * 2) + q * 16,
                     &g_w_hi[s * DM2 + kn + q * 8]);
                cp16(sb + (cur ^ 1) * 18432 + K1_WSZ + s * (K1_WLD * 2) + q * 16,
                     &g_w_lo[s * DM2 + kn + q * 8]);
            }
            CP_COMMIT();
        }
        // X: 64k x 128l from fp32 x (sync, with split)
#pragma unroll
        for (int k = 0; k < 8; k++) {
            int e = tid + k * 256;
            int r = e >> 5, q = e & 31;
            float4 v = x4[((size_t)b * DMODEL + kc + r) * 1024 + (l0 >> 2) + q];
            uint2 hv, lv;
            split4(v, hv, lv);
            *reinterpret_cast<uint2*>(&Xhi[r * K1_XLD + q * 4]) = hv;
            *reinterpret_cast<uint2*>(&Xlo[r * K1_XLD + q * 4]) = lv;
        }
        if (it < 7) CP_WAIT1(); else CP_WAIT0();
        __syncthreads();

        const __nv_bfloat16* Whi = reinterpret_cast<const __nv_bfloat16*>(smem + cur * 18432);
        const __nv_bfloat16* Wlo = reinterpret_cast<const __nv_bfloat16*>(smem + cur * 18432 + K1_WSZ);
#pragma unroll
        for (int ks = 0; ks < 4; ks++) {
            int kk = ks * 16;
            wmma::fragment<wmma::matrix_a, 16, 16, 16, __nv_bfloat16, wmma::row_major> ah, al;
            wmma::load_matrix_sync(ah, Whi + wm * K1_WLD + kk, K1_WLD);
            wmma::load_matrix_sync(al, Wlo + wm * K1_WLD + kk, K1_WLD);
#pragma unroll
            for (int j = 0; j < 4; j++) {
                wmma::fragment<wmma::matrix_b, 16, 16, 16, __nv_bfloat16, wmma::row_major> bh, bl;
                wmma::load_matrix_sync(bh, Xhi + kk * K1_XLD + wn + j * 16, K1_XLD);
                wmma::load_matrix_sync(bl, Xlo + kk * K1_XLD + wn + j * 16, K1_XLD);
                wmma::mma_sync(acc[j], ah, bh, acc[j]);
                wmma::mma_sync(acc[j], ah, bl, acc[j]);
                wmma::mma_sync(acc[j], al, bh, acc[j]);
            }
        }
        __syncthreads();
    }
    float* stage = reinterpret_cast<float*>(smem);          // [64][136] fp32 (34816 B)
#pragma unroll
    for (int j = 0; j < 4; j++)
        wmma::store_matrix_sync(stage + wm * K1_XLD + wn + j * 16, acc[j],
                                K1_XLD, wmma::mem_row_major);
    __syncthreads();
#pragma unroll
    for (int k = 0; k < 8; k++) {
        int g = tid + k * 256;
        int row = g >> 5, c4 = g & 31;
        float bv = bias[row];
        float4 v = *reinterpret_cast<const float4*>(&stage[row * K1_XLD + c4 * 4]);
        v.x += bv; v.y += bv; v.z += bv; v.w += bv;
        *reinterpret_cast<float4*>(
            &g_bcdt[((size_t)b * SS + row) * LSZ + l0 + c4 * 4]) = v;
    }
}

// ============================================================
// k2: conv3x3 + softmax; writes bf16 hi/lo of conv and AB.
// ============================================================
__global__ void k2_conv_softmax(const float* __restrict__ wdw,
                                const float* __restrict__ bdw,
                                const float* __restrict__ A,
                                const float* __restrict__ coeffs) {
    __shared__ float sm[66][68];
    __shared__ float red[8];
    int s = blockIdx.x, b = blockIdx.y;
    int tid = threadIdx.x;
    size_t off = ((size_t)b * SS + s) * LSZ;
    const float* plane = g_bcdt + off;

    for (int e = tid; e < 66 * 68; e += 256) ((float*)sm)[e] = 0.f;
    __syncthreads();
#pragma unroll
    for (int k = 0; k < 16; k++) {
        int idx = tid + k * 256;
        sm[(idx >> 6) + 1][(idx & 63) + 1] = plane[idx];
    }
    __syncthreads();

    float w[9];
#pragma unroll
    for (int i = 0; i < 9; i++) w[i] = wdw[s * 9 + i];
    float bb = bdw[s];
    float c0 = coeffs[0], c2 = coeffs[2];
    float Av = A[s];

    float v[16];
    float lmax = -1e30f;
#pragma unroll
    for (int k = 0; k < 8; k++) {
        int base = tid * 2 + k * 512;
        int r = base >> 6, c = base & 63;
        float a0 = bb, a1 = bb;
#pragma unroll
        for (int i = 0; i < 3; i++)
#pragma unroll
            for (int j = 0; j < 3; j++) {
                float wv = w[i * 3 + j];
                a0 += wv * sm[r + i][c + j];
                a1 += wv * sm[r + i][c + 1 + j];
            }
        v[2 * k] = a0; v[2 * k + 1] = a1;
        lmax = fmaxf(lmax, fmaxf(c2 * a0, c2 * a1) + Av);
    }
#pragma unroll
    for (int o = 16; o > 0; o >>= 1)
        lmax = fmaxf(lmax, __shfl_xor_sync(0xffffffffu, lmax, o));
    if ((tid & 31) == 0) red[tid >> 5] = lmax;
    __syncthreads();
    float bmax = red[0];
#pragma unroll
    for (int i = 1; i < 8; i++) bmax = fmaxf(bmax, red[i]);
    __syncthreads();

    float ev[16];
    float lsum = 0.f;
#pragma unroll
    for (int k = 0; k < 16; k++) {
        ev[k] = __expf(c2 * v[k] + Av - bmax);
        lsum += ev[k];
    }
#pragma unroll
    for (int o = 16; o > 0; o >>= 1)
        lsum += __shfl_xor_sync(0xffffffffu, lsum, o);
    if ((tid & 31) == 0) red[tid >> 5] = lsum;
    __syncthreads();
    float bsum = 0.f;
#pragma unroll
    for (int i = 0; i < 8; i++) bsum += red[i];
    float inv = 1.f / bsum;

#pragma unroll
    for (int k = 0; k < 8; k++) {
        int base = tid * 2 + k * 512;
        float v0 = v[2 * k], v1 = v[2 * k + 1];
        __nv_bfloat16 ch0, cl0, ch1, cl1;
        split1(v0, ch0, cl0); split1(v1, ch1, cl1);
        *reinterpret_cast<uint32_t*>(&g_conv_hi[off + base]) = pk(ch0, ch1);
        *reinterpret_cast<uint32_t*>(&g_conv_lo[off + base]) = pk(cl0, cl1);
        float a0 = ev[2 * k] * inv * c0 * v0;
        float a1 = ev[2 * k + 1] * inv * c0 * v1;
        __nv_bfloat16 ah0, al0, ah1, al1;
        split1(a0, ah0, al0); split1(a1, ah1, al1);
        *reinterpret_cast<uint32_t*>(&g_AB_hi[off + base]) = pk(ah0, ah1);
        *reinterpret_cast<uint32_t*>(&g_AB_lo[off + base]) = pk(al0, al1);
    }
}

// ============================================================
// k3 (wmma + cp.async B double-buffer): h[d,s] = sum_l xh[d,l]*AB[s,l]
// block 128d x 64s, L-split 8, 8 chunks of 64 l. atomics out.
// smem: Ahi Alo (2x18432) | B0hi B0lo B1hi B1lo (4x9216) = 73728
// ============================================================
#define K3_ALD 72
#define K3_BLD 72
#define K3_A_HI 0
#define K3_A_LO 18432
#define K3_B_BASE 36864
#define K3_BSZ 9216
#define K3_SMEM 73728

__global__ void k3_wmma(const float4* __restrict__ x4, float* __restrict__ hout) {
    extern __shared__ __align__(16) char smem[];
    uint32_t sb = smem_u32(smem);
    __nv_bfloat16* Ahi = reinterpret_cast<__nv_bfloat16*>(smem + K3_A_HI);
    __nv_bfloat16* Alo = reinterpret_cast<__nv_bfloat16*>(smem + K3_A_LO);
    int lp = blockIdx.x;                 // 0..7
    int d0 = blockIdx.y * 128;
    int b = blockIdx.z;
    int tid = threadIdx.x;
    int wid = tid >> 5;
    int wm = (wid >> 1) * 32;            // d
    int wn = (wid & 1) * 32;             // s

    wmma::fragment<wmma::accumulator, 16, 16, 16, float> acc[2][2];
#pragma unroll
    for (int i = 0; i < 2; i++)
#pragma unroll
        for (int j = 0; j < 2; j++) wmma::fill_fragment(acc[i][j], 0.f);

    // issue B chunk 0 -> buf 0
    {
        int lbase = lp * 512;
#pragma unroll
        for (int k = 0; k < 2; k++) {
            int e = tid + k * 256;           // 512: si = e>>3, q = e&7
            int si = e >> 3, q = e & 7;
            size_t src = (((size_t)b * SS + si) << 12) + lbase + q * 8;
            cp16(sb + K3_B_BASE + si * (K3_BLD * 2) + q * 16, &g_AB_hi[src]);
            cp16(sb + K3_B_BASE + K3_BSZ + si * (K3_BLD * 2) + q * 16, &g_AB_lo[src]);
        }
        CP_COMMIT();
    }

    for (int it = 0; it < 8; it++) {
        int cur = it & 1;
        if (it < 7) {                        // prefetch B chunk it+1 -> buf cur^1
            int lbase = lp * 512 + (it + 1) * 64;
#pragma unroll
            for (int k = 0; k < 2; k++) {
                int e = tid + k * 256;
                int si = e >> 3, q = e & 7;
                size_t src = (((size_t)b * SS + si) << 12) + lbase + q * 8;
                cp16(sb + K3_B_BASE + (cur ^ 1) * 18432 + si * (K3_BLD * 2) + q * 16,
                     &g_AB_hi[src]);
                cp16(sb + K3_B_BASE + (cur ^ 1) * 18432 + K3_BSZ + si * (K3_BLD * 2) + q * 16,
                     &g_AB_lo[src]);
            }
            CP_COMMIT();
        }
        // A: 128d x 64l from fp32 x (sync, with split)
        {
            int lbase = lp * 512 + it * 64;
#pragma unroll
            for (int k = 0; k < 8; k++) {
                int e = tid + k * 256;
                int d = e >> 4, q = e & 15;
                float4 v = x4[((size_t)b * DMODEL + d0 + d) * 1024 + (lbase >> 2) + q];
                uint2 hv, lv;
                split4(v, hv, lv);
                *reinterpret_cast<uint2*>(&Ahi[d * K3_ALD + q * 4]) = hv;
                *reinterpret_cast<uint2*>(&Alo[d * K3_ALD + q * 4]) = lv;
            }
        }
        if (it < 7) CP_WAIT1(); else CP_WAIT0();
        __syncthreads();

        const __nv_bfloat16* Bhi =
            reinterpret_cast<const __nv_bfloat16*>(smem + K3_B_BASE + cur * 18432);
        const __nv_bfloat16* Blo =
            reinterpret_cast<const __nv_bfloat16*>(smem + K3_B_BASE + cur * 18432 + K3_BSZ);
#pragma unroll
        for (int ks = 0; ks < 4; ks++) {
            int kk = ks * 16;
            wmma::fragment<wmma::matrix_a, 16, 16, 16, __nv_bfloat16, wmma::row_major> ah[2], al[2];
            wmma::fragment<wmma::matrix_b, 16, 16, 16, __nv_bfloat16, wmma::col_major> bh[2], bl[2];
#pragma unroll
            for (int i = 0; i < 2; i++) {
                wmma::load_matrix_sync(ah[i], Ahi + (wm + i * 16) * K3_ALD + kk, K3_ALD);
                wmma::load_matrix_sync(al[i], Alo + (wm + i * 16) * K3_ALD + kk, K3_ALD);
            }
#pragma unroll
            for (int j = 0; j < 2; j++) {
                wmma::load_matrix_sync(bh[j], Bhi + (wn + j * 16) * K3_BLD + kk, K3_BLD);
                wmma::load_matrix_sync(bl[j], Blo + (wn + j * 16) * K3_BLD + kk, K3_BLD);
            }
#pragma unroll
            for (int i = 0; i < 2; i++)
#pragma unroll
                for (int j = 0; j < 2; j++) {
                    wmma::mma_sync(acc[i][j], ah[i], bh[j], acc[i][j]);
                    wmma::mma_sync(acc[i][j], ah[i], bl[j], acc[i][j]);
                    wmma::mma_sync(acc[i][j], al[i], bh[j], acc[i][j]);
                }
        }
        __syncthreads();
    }
    float* stage = reinterpret_cast<float*>(smem);          // [128][72] = 36864 B
#pragma unroll
    for (int i = 0; i < 2; i++)
#pragma unroll
        for (int j = 0; j < 2; j++)
            wmma::store_matrix_sync(stage + (wm + i * 16) * K3_ALD + wn + j * 16,
                                    acc[i][j], K3_ALD, wmma::mem_row_major);
    __syncthreads();
    float* hb = hout + ((size_t)b * DM2 + d0) * SS;
#pragma unroll
    for (int k = 0; k < 32; k++) {
        int e = tid + k * 256;
        int d = e >> 6, si = e & 63;
        atomicAdd(&hb[d * SS + si], stage[d * K3_ALD + si]);
    }
}

// ============================================================
// k4a (wmma): y_pre[d,l] = sum_s (c1*h)[d,s]*conv[s,l]
// A loaded fp32 from h (output buffer), c1 applied + split in-register.
// ============================================================
#define K4_ALD 72
#define K4_BLD 72
#define K4_OFF_AHI 0
#define K4_OFF_ALO 18432
#define K4_OFF_BHI 36864
#define K4_OFF_BLO 46080
#define K4_SMEM 55296

__global__ void k4a_wmma(const float4* __restrict__ h4,
                         const float* __restrict__ coeffs) {
    extern __shared__ __align__(16) char smem[];
    __nv_bfloat16* Ahi = reinterpret_cast<__nv_bfloat16*>(smem + K4_OFF_AHI);
    __nv_bfloat16* Alo = reinterpret_cast<__nv_bfloat16*>(smem + K4_OFF_ALO);
    __nv_bfloat16* Bhi = reinterpret_cast<__nv_bfloat16*>(smem + K4_OFF_BHI);
    __nv_bfloat16* Blo = reinterpret_cast<__nv_bfloat16*>(smem + K4_OFF_BLO);
    int l0 = blockIdx.x * 64;
    int d0 = blockIdx.y * 128;
    int b = blockIdx.z;
    int tid = threadIdx.x;
    int wid = tid >> 5;
    int wm = (wid >> 1) * 32;            // d
    int wn = (wid & 1) * 32;             // l
    float c1 = coeffs[1];

    const float4* hb4 = h4 + (((size_t)b * DM2 + d0) * SS >> 2);
#pragma unroll
    for (int k = 0; k < 8; k++) {
        int e = tid + k * 256;
        int d = e >> 4, q = e & 15;
        float4 v = hb4[e];
        v.x *= c1; v.y *= c1; v.z *= c1; v.w *= c1;
        uint2 hv, lv;
        split4(v, hv, lv);
        *reinterpret_cast<uint2*>(&Ahi[d * K4_ALD + q * 4]) = hv;
        *reinterpret_cast<uint2*>(&Alo[d * K4_ALD + q * 4]) = lv;
    }
#pragma unroll
    for (int k = 0; k < 4; k++) {
        int e = tid + k * 256;
        int si = e >> 4, q = e & 15;
        size_t src = (((size_t)b * SS + si) << 12) + l0 + q * 4;
        *reinterpret_cast<uint2*>(&Bhi[si * K4_BLD + q * 4]) =
            *reinterpret_cast<const uint2*>(&g_conv_hi[src]);
        *reinterpret_cast<uint2*>(&Blo[si * K4_BLD + q * 4]) =
            *reinterpret_cast<const uint2*>(&g_conv_lo[src]);
    }
    __syncthreads();

    wmma::fragment<wmma::accumulator, 16, 16, 16, float> acc[2][2];
#pragma unroll
    for (int i = 0; i < 2; i++)
#pragma unroll
        for (int j = 0; j < 2; j++) wmma::fill_fragment(acc[i][j], 0.f);

#pragma unroll
    for (int ks = 0; ks < 4; ks++) {
        int kk = ks * 16;
        wmma::fragment<wmma::matrix_a, 16, 16, 16, __nv_bfloat16, wmma::row_major> ah[2], al[2];
        wmma::fragment<wmma::matrix_b, 16, 16, 16, __nv_bfloat16, wmma::row_major> bh[2], bl[2];
#pragma unroll
        for (int i = 0; i < 2; i++) {
            wmma::load_matrix_sync(ah[i], Ahi + (wm + i * 16) * K4_ALD + kk, K4_ALD);
            wmma::load_matrix_sync(al[i], Alo + (wm + i * 16) * K4_ALD + kk, K4_ALD);
        }
#pragma unroll
        for (int j = 0; j < 2; j++) {
            wmma::load_matrix_sync(bh[j], Bhi + kk * K4_BLD + wn + j * 16, K4_BLD);
            wmma::load_matrix_sync(bl[j], Blo + kk * K4_BLD + wn + j * 16, K4_BLD);
        }
#pragma unroll
        for (int i = 0; i < 2; i++)
#pragma unroll
            for (int j = 0; j < 2; j++) {
                wmma::mma_sync(acc[i][j], ah[i], bh[j], acc[i][j]);
                wmma::mma_sync(acc[i][j], ah[i], bl[j], acc[i][j]);
                wmma::mma_sync(acc[i][j], al[i], bh[j], acc[i][j]);
            }
    }
    __syncthreads();
    float* stage = reinterpret_cast<float*>(smem);          // [128][72]
#pragma unroll
    for (int i = 0; i < 2; i++)
#pragma unroll
        for (int j = 0; j < 2; j++)
            wmma::store_matrix_sync(stage + (wm + i * 16) * K4_ALD + wn + j * 16,
                                    acc[i][j], K4_ALD, wmma::mem_row_major);
    __syncthreads();
#pragma unroll
    for (int k = 0; k < 8; k++) {
        int g = tid + k * 256;               // 2048 f4 = 128 rows x 16
        int row = g >> 4, c4 = g & 15;
        float4 v = *reinterpret_cast<const float4*>(&stage[row * K4_ALD + c4 * 4]);
        *reinterpret_cast<float4*>(
            &g_ypre[((size_t)b * DM2 + d0 + row) * LSZ + l0 + c4 * 4]) = v;
    }
}

// ============================================================
// k4b: final depthwise conv, float4 I/O, all 1024 channels.
// ============================================================
__global__ void k4b_conv(const float* __restrict__ x,
                         const float* __restrict__ wDW,
                         const float* __restrict__ bDW,
                         float* __restrict__ out) {
    __shared__ __align__(16) float sm[66][72];
    int c = blockIdx.x, b = blockIdx.y;
    int tid = threadIdx.x;
    const float* plane = (c < DM2)
        ? (g_ypre + ((size_t)b * DM2 + c) * LSZ)
        : (x + ((size_t)b * DMODEL + c) * LSZ);
    const float4* plane4 = reinterpret_cast<const float4*>(plane);

    if (tid < 72) { sm[0][tid] = 0.f; sm[65][tid] = 0.f; }
    else if (tid < 136) { int r = tid - 72 + 1; sm[r][3] = 0.f; sm[r][68] = 0.f; }
#pragma unroll
    for (int k = 0; k < 4; k++) {
        int g = tid + k * 256;
        int row = g >> 4, cq = g & 15;
        *reinterpret_cast<float4*>(&sm[row + 1][4 + cq * 4]) = plane4[g];
    }
    __syncthreads();

    float w[9];
#pragma unroll
    for (int i = 0; i < 9; i++) w[i] = wDW[c * 9 + i];
    float bb = bDW[c];
    float4* ob4 = reinterpret_cast<float4*>(out + ((size_t)b * DMODEL + c) * LSZ);
#pragma unroll
    for (int k = 0; k < 4; k++) {
        int g = tid + k * 256;
        int row = g >> 4, c0 = (g & 15) * 4;
        float o[4];
#pragma unroll
        for (int u = 0; u < 4; u++) {
            int cc = c0 + u;
            float acc = bb;
#pragma unroll
            for (int i = 0; i < 3; i++)
#pragma unroll
                for (int j = 0; j < 3; j++)
                    acc += w[i * 3 + j] * sm[row + i][3 + cc + j];
            o[u] = acc;
        }
        ob4[g] = make_float4(o[0], o[1], o[2], o[3]);
    }
}

// ============================================================
extern "C" void kernel_launch(void* const* d_in, const int* in_sizes, int n_in,
                              void* d_out, int out_size) {
    const float* x      = (const float*)d_in[0];
    const float* w_bcdt = (const float*)d_in[1];
    const float* b_bcdt = (const float*)d_in[2];
    const float* w_dw   = (const float*)d_in[3];
    const float* b_dw   = (const float*)d_in[4];
    const float* A      = (const float*)d_in[5];
    const float* coeffs = (const float*)d_in[6];
    const float* w_DW   = (const float*)d_in[7];
    const float* b_DW   = (const float*)d_in[8];

    float* y_out = (float*)d_out;                          // (16,1024,4096)
    float* h_out = y_out + (size_t)BATCH * DMODEL * LSZ;   // (16,512,64)

    cudaFuncSetAttribute(k1_wmma, cudaFuncAttributeMaxDynamicSharedMemorySize, K1_SMEM);
    cudaFuncSetAttribute(k3_wmma, cudaFuncAttributeMaxDynamicSharedMemorySize, K3_SMEM);
    cudaFuncSetAttribute(k4a_wmma, cudaFuncAttributeMaxDynamicSharedMemorySize, K4_SMEM);

    cudaMemsetAsync(h_out, 0, (size_t)BATCH * DM2 * SS * sizeof(float));

    k0_convert_w<<<8, 256>>>((const float4*)w_bcdt);
    k1_wmma<<<dim3(32, 16), 256, K1_SMEM>>>((const float4*)x, b_bcdt);
    k2_conv_softmax<<<dim3(64, 16), 256>>>(w_dw, b_dw, A, coeffs);
    k3_wmma<<<dim3(8, 4, 16), 256, K3_SMEM>>>((const float4*)x, h_out);
    k4a_wmma<<<dim3(64, 4, 16), 256, K4_SMEM>>>((const float4*)h_out, coeffs);
    k4b_conv<<<dim3(1024, 16), 256>>>(x, w_DW, b_DW, y_out);
}

// round 14
// speedup vs baseline: 1.0452x; 1.0071x over previous
#include <cuda_runtime.h>
#include <cuda_bf16.h>
#include <mma.h>
#include <cstdint>

using namespace nvcuda;

#define BATCH 16
#define DMODEL 1024
#define DM2 512
#define LSZ 4096
#define SS 64

// ---- scratch (device globals; no allocations allowed) ----
__device__ float g_bcdt[BATCH * SS * LSZ];                 // 16 MB fp32
__device__ __nv_bfloat16 g_conv_hi[BATCH * SS * LSZ];      // 8 MB
__device__ __nv_bfloat16 g_conv_lo[BATCH * SS * LSZ];
__device__ __nv_bfloat16 g_AB_hi[BATCH * SS * LSZ];
__device__ __nv_bfloat16 g_AB_lo[BATCH * SS * LSZ];
__device__ __nv_bfloat16 g_w_hi[SS * DM2];
__device__ __nv_bfloat16 g_w_lo[SS * DM2];
__device__ float g_ypre[BATCH * DM2 * LSZ];                // 128 MB

__device__ __forceinline__ uint32_t pk(__nv_bfloat16 a, __nv_bfloat16 b) {
    __nv_bfloat162 t; t.x = a; t.y = b;
    return *reinterpret_cast<uint32_t*>(&t);
}
__device__ __forceinline__ void split1(float v, __nv_bfloat16& hi, __nv_bfloat16& lo) {
    hi = __float2bfloat16_rn(v);
    lo = __float2bfloat16_rn(v - __bfloat162float(hi));
}
__device__ __forceinline__ void split4(float4 v, uint2& hv, uint2& lv) {
    __nv_bfloat16 h0, l0, h1, l1, h2, l2, h3, l3;
    split1(v.x, h0, l0); split1(v.y, h1, l1);
    split1(v.z, h2, l2); split1(v.w, h3, l3);
    hv = make_uint2(pk(h0, h1), pk(h2, h3));
    lv = make_uint2(pk(l0, l1), pk(l2, l3));
}

// ============================================================
// k0w: w_bcdt -> bf16 hi/lo (tiny)
// ============================================================
__global__ void k0_convert_w(const float4* __restrict__ w4) {
    int tid = threadIdx.x;
#pragma unroll
    for (int k = 0; k < 4; k++) {
        int g = blockIdx.x * 1024 + k * 256 + tid;
        uint2 hv, lv;
        split4(w4[g], hv, lv);
        *reinterpret_cast<uint2*>(&g_w_hi[g * 4]) = hv;
        *reinterpret_cast<uint2*>(&g_w_lo[g * 4]) = lv;
    }
}

// ============================================================
// k1 (wmma): BCdt[s,l] = sum_d w[s,d]*xh[d,l] + bias[s]
// ============================================================
#define K1_WLD 72
#define K1_XLD 136
#define K1_OFF_WHI 0
#define K1_OFF_WLO 9216
#define K1_OFF_XHI 18432
#define K1_OFF_XLO 35840
#define K1_SMEM 53248

__global__ void k1_wmma(const float4* __restrict__ x4, const float* __restrict__ bias) {
    extern __shared__ __align__(16) char smem[];
    __nv_bfloat16* Whi = reinterpret_cast<__nv_bfloat16*>(smem + K1_OFF_WHI);
    __nv_bfloat16* Wlo = reinterpret_cast<__nv_bfloat16*>(smem + K1_OFF_WLO);
    __nv_bfloat16* Xhi = reinterpret_cast<__nv_bfloat16*>(smem + K1_OFF_XHI);
    __nv_bfloat16* Xlo = reinterpret_cast<__nv_bfloat16*>(smem + K1_OFF_XLO);
    int b = blockIdx.y;
    int l0 = blockIdx.x * 128;
    int tid = threadIdx.x;
    int wid = tid >> 5;
    int wm = (wid >> 1) * 16;    // s
    int wn = (wid & 1) * 64;     // l

    wmma::fragment<wmma::accumulator, 16, 16, 16, float> acc[4];
#pragma unroll
    for (int j = 0; j < 4; j++) wmma::fill_fragment(acc[j], 0.f);

    for (int kc = 0; kc < DM2; kc += 64) {
#pragma unroll
        for (int k = 0; k < 4; k++) {            // W: 64s x 64k
            int e = tid + k * 256;
            int s = e >> 4, q = e & 15;
            *reinterpret_cast<uint2*>(&Whi[s * K1_WLD + q * 4]) =
                *reinterpret_cast<const uint2*>(&g_w_hi[s * DM2 + kc + q * 4]);
            *reinterpret_cast<uint2*>(&Wlo[s * K1_WLD + q * 4]) =
                *reinterpret_cast<const uint2*>(&g_w_lo[s * DM2 + kc + q * 4]);
        }
#pragma unroll
        for (int k = 0; k < 8; k++) {            // X: 64k x 128l from fp32 x
            int e = tid + k * 256;
            int r = e >> 5, q = e & 31;
            float4 v = x4[((size_t)b * DMODEL + kc + r) * 1024 + (l0 >> 2) + q];
            uint2 hv, lv;
            split4(v, hv, lv);
            *reinterpret_cast<uint2*>(&Xhi[r * K1_XLD + q * 4]) = hv;
            *reinterpret_cast<uint2*>(&Xlo[r * K1_XLD + q * 4]) = lv;
        }
        __syncthreads();
#pragma unroll
        for (int ks = 0; ks < 4; ks++) {
            int kk = ks * 16;
            wmma::fragment<wmma::matrix_a, 16, 16, 16, __nv_bfloat16, wmma::row_major> ah, al;
            wmma::load_matrix_sync(ah, Whi + wm * K1_WLD + kk, K1_WLD);
            wmma::load_matrix_sync(al, Wlo + wm * K1_WLD + kk, K1_WLD);
#pragma unroll
            for (int j = 0; j < 4; j++) {
                wmma::fragment<wmma::matrix_b, 16, 16, 16, __nv_bfloat16, wmma::row_major> bh, bl;
                wmma::load_matrix_sync(bh, Xhi + kk * K1_XLD + wn + j * 16, K1_XLD);
                wmma::load_matrix_sync(bl, Xlo + kk * K1_XLD + wn + j * 16, K1_XLD);
                wmma::mma_sync(acc[j], ah, bh, acc[j]);
                wmma::mma_sync(acc[j], ah, bl, acc[j]);
                wmma::mma_sync(acc[j], al, bh, acc[j]);
            }
        }
        __syncthreads();
    }
    float* stage = reinterpret_cast<float*>(smem);          // [64][136]
#pragma unroll
    for (int j = 0; j < 4; j++)
        wmma::store_matrix_sync(stage + wm * K1_XLD + wn + j * 16, acc[j],
                                K1_XLD, wmma::mem_row_major);
    __syncthreads();
#pragma unroll
    for (int k = 0; k < 8; k++) {
        int g = tid + k * 256;
        int row = g >> 5, c4 = g & 31;
        float bv = bias[row];
        float4 v = *reinterpret_cast<const float4*>(&stage[row * K1_XLD + c4 * 4]);
        v.x += bv; v.y += bv; v.z += bv; v.w += bv;
        *reinterpret_cast<float4*>(
            &g_bcdt[((size_t)b * SS + row) * LSZ + l0 + c4 * 4]) = v;
    }
}

// ============================================================
// k2: conv3x3 + softmax; float4 plane loads; writes bf16 hi/lo.
// ============================================================
__global__ void k2_conv_softmax(const float* __restrict__ wdw,
                                const float* __restrict__ bdw,
                                const float* __restrict__ A,
                                const float* __restrict__ coeffs) {
    __shared__ float sm[66][68];
    __shared__ float red[8];
    int s = blockIdx.x, b = blockIdx.y;
    int tid = threadIdx.x;
    size_t off = ((size_t)b * SS + s) * LSZ;
    const float4* plane4 = reinterpret_cast<const float4*>(g_bcdt + off);

    for (int e = tid; e < 66 * 68; e += 256) ((float*)sm)[e] = 0.f;
    __syncthreads();
#pragma unroll
    for (int k = 0; k < 4; k++) {
        int g = tid + k * 256;               // 1024 f4
        float4 v = plane4[g];
        int base = g * 4;
        int r = (base >> 6) + 1, c = (base & 63) + 1;
        sm[r][c] = v.x; sm[r][c + 1] = v.y; sm[r][c + 2] = v.z; sm[r][c + 3] = v.w;
    }
    __syncthreads();

    float w[9];
#pragma unroll
    for (int i = 0; i < 9; i++) w[i] = wdw[s * 9 + i];
    float bb = bdw[s];
    float c0 = coeffs[0], c2 = coeffs[2];
    float Av = A[s];

    float v[16];
    float lmax = -1e30f;
#pragma unroll
    for (int k = 0; k < 8; k++) {
        int base = tid * 2 + k * 512;
        int r = base >> 6, c = base & 63;
        float a0 = bb, a1 = bb;
#pragma unroll
        for (int i = 0; i < 3; i++)
#pragma unroll
            for (int j = 0; j < 3; j++) {
                float wv = w[i * 3 + j];
                a0 += wv * sm[r + i][c + j];
                a1 += wv * sm[r + i][c + 1 + j];
            }
        v[2 * k] = a0; v[2 * k + 1] = a1;
        lmax = fmaxf(lmax, fmaxf(c2 * a0, c2 * a1) + Av);
    }
#pragma unroll
    for (int o = 16; o > 0; o >>= 1)
        lmax = fmaxf(lmax, __shfl_xor_sync(0xffffffffu, lmax, o));
    if ((tid & 31) == 0) red[tid >> 5] = lmax;
    __syncthreads();
    float bmax = red[0];
#pragma unroll
    for (int i = 1; i < 8; i++) bmax = fmaxf(bmax, red[i]);
    __syncthreads();

    float ev[16];
    float lsum = 0.f;
#pragma unroll
    for (int k = 0; k < 16; k++) {
        ev[k] = __expf(c2 * v[k] + Av - bmax);
        lsum += ev[k];
    }
#pragma unroll
    for (int o = 16; o > 0; o >>= 1)
        lsum += __shfl_xor_sync(0xffffffffu, lsum, o);
    if ((tid & 31) == 0) red[tid >> 5] = lsum;
    __syncthreads();
    float bsum = 0.f;
#pragma unroll
    for (int i = 0; i < 8; i++) bsum += red[i];
    float inv = 1.f / bsum;

#pragma unroll
    for (int k = 0; k < 8; k++) {
        int base = tid * 2 + k * 512;
        float v0 = v[2 * k], v1 = v[2 * k + 1];
        __nv_bfloat16 ch0, cl0, ch1, cl1;
        split1(v0, ch0, cl0); split1(v1, ch1, cl1);
        *reinterpret_cast<uint32_t*>(&g_conv_hi[off + base]) = pk(ch0, ch1);
        *reinterpret_cast<uint32_t*>(&g_conv_lo[off + base]) = pk(cl0, cl1);
        float a0 = ev[2 * k] * inv * c0 * v0;
        float a1 = ev[2 * k + 1] * inv * c0 * v1;
        __nv_bfloat16 ah0, al0, ah1, al1;
        split1(a0, ah0, al0); split1(a1, ah1, al1);
        *reinterpret_cast<uint32_t*>(&g_AB_hi[off + base]) = pk(ah0, ah1);
        *reinterpret_cast<uint32_t*>(&g_AB_lo[off + base]) = pk(al0, al1);
    }
}

// ============================================================
// k3 (wmma): h[d,s] = sum_l xh[d,l]*AB[s,l]; L-split 8, atomics.
// ============================================================
#define K3_ALD 72
#define K3_BLD 72
#define K3_OFF_AHI 0
#define K3_OFF_ALO 18432
#define K3_OFF_BHI 36864
#define K3_OFF_BLO 46080
#define K3_SMEM 55296

__global__ void k3_wmma(const float4* __restrict__ x4, float* __restrict__ hout) {
    extern __shared__ __align__(16) char smem[];
    __nv_bfloat16* Ahi = reinterpret_cast<__nv_bfloat16*>(smem + K3_OFF_AHI);
    __nv_bfloat16* Alo = reinterpret_cast<__nv_bfloat16*>(smem + K3_OFF_ALO);
    __nv_bfloat16* Bhi = reinterpret_cast<__nv_bfloat16*>(smem + K3_OFF_BHI);
    __nv_bfloat16* Blo = reinterpret_cast<__nv_bfloat16*>(smem + K3_OFF_BLO);
    int lp = blockIdx.x;                 // 0..7
    int d0 = blockIdx.y * 128;
    int b = blockIdx.z;
    int tid = threadIdx.x;
    int wid = tid >> 5;
    int wm = (wid >> 1) * 32;            // d
    int wn = (wid & 1) * 32;             // s

    wmma::fragment<wmma::accumulator, 16, 16, 16, float> acc[2][2];
#pragma unroll
    for (int i = 0; i < 2; i++)
#pragma unroll
        for (int j = 0; j < 2; j++) wmma::fill_fragment(acc[i][j], 0.f);

    for (int lc = 0; lc < 512; lc += 64) {
        int lbase = lp * 512 + lc;
#pragma unroll
        for (int k = 0; k < 8; k++) {        // A: 128d x 64l from fp32 x
            int e = tid + k * 256;
            int d = e >> 4, q = e & 15;
            float4 v = x4[((size_t)b * DMODEL + d0 + d) * 1024 + (lbase >> 2) + q];
            uint2 hv, lv;
            split4(v, hv, lv);
            *reinterpret_cast<uint2*>(&Ahi[d * K3_ALD + q * 4]) = hv;
            *reinterpret_cast<uint2*>(&Alo[d * K3_ALD + q * 4]) = lv;
        }
#pragma unroll
        for (int k = 0; k < 4; k++) {        // B: 64s x 64l
            int e = tid + k * 256;
            int si = e >> 4, q = e & 15;
            size_t src = (((size_t)b * SS + si) << 12) + lbase + q * 4;
            *reinterpret_cast<uint2*>(&Bhi[si * K3_BLD + q * 4]) =
                *reinterpret_cast<const uint2*>(&g_AB_hi[src]);
            *reinterpret_cast<uint2*>(&Blo[si * K3_BLD + q * 4]) =
                *reinterpret_cast<const uint2*>(&g_AB_lo[src]);
        }
        __syncthreads();
#pragma unroll
        for (int ks = 0; ks < 4; ks++) {
            int kk = ks * 16;
            wmma::fragment<wmma::matrix_a, 16, 16, 16, __nv_bfloat16, wmma::row_major> ah[2], al[2];
            wmma::fragment<wmma::matrix_b, 16, 16, 16, __nv_bfloat16, wmma::col_major> bh[2], bl[2];
#pragma unroll
            for (int i = 0; i < 2; i++) {
                wmma::load_matrix_sync(ah[i], Ahi + (wm + i * 16) * K3_ALD + kk, K3_ALD);
                wmma::load_matrix_sync(al[i], Alo + (wm + i * 16) * K3_ALD + kk, K3_ALD);
            }
#pragma unroll
            for (int j = 0; j < 2; j++) {
                wmma::load_matrix_sync(bh[j], Bhi + (wn + j * 16) * K3_BLD + kk, K3_BLD);
                wmma::load_matrix_sync(bl[j], Blo + (wn + j * 16) * K3_BLD + kk, K3_BLD);
            }
#pragma unroll
            for (int i = 0; i < 2; i++)
#pragma unroll
                for (int j = 0; j < 2; j++) {
                    wmma::mma_sync(acc[i][j], ah[i], bh[j], acc[i][j]);
                    wmma::mma_sync(acc[i][j], ah[i], bl[j], acc[i][j]);
                    wmma::mma_sync(acc[i][j], al[i], bh[j], acc[i][j]);
                }
        }
        __syncthreads();
    }
    float* stage = reinterpret_cast<float*>(smem);          // [128][72]
#pragma unroll
    for (int i = 0; i < 2; i++)
#pragma unroll
        for (int j = 0; j < 2; j++)
            wmma::store_matrix_sync(stage + (wm + i * 16) * K3_ALD + wn + j * 16,
                                    acc[i][j], K3_ALD, wmma::mem_row_major);
    __syncthreads();
    float* hb = hout + ((size_t)b * DM2 + d0) * SS;
#pragma unroll
    for (int k = 0; k < 32; k++) {
        int e = tid + k * 256;
        int d = e >> 6, si = e & 63;
        atomicAdd(&hb[d * SS + si], stage[d * K3_ALD + si]);
    }
}

// ============================================================
// k4a (wmma): y_pre[d,l] = sum_s (c1*h)[d,s]*conv[s,l]
// ============================================================
#define K4_ALD 72
#define K4_BLD 72
#define K4_OFF_AHI 0
#define K4_OFF_ALO 18432
#define K4_OFF_BHI 36864
#define K4_OFF_BLO 46080
#define K4_SMEM 55296

__global__ void k4a_wmma(const float4* __restrict__ h4,
                         const float* __restrict__ coeffs) {
    extern __shared__ __align__(16) char smem[];
    __nv_bfloat16* Ahi = reinterpret_cast<__nv_bfloat16*>(smem + K4_OFF_AHI);
    __nv_bfloat16* Alo = reinterpret_cast<__nv_bfloat16*>(smem + K4_OFF_ALO);
    __nv_bfloat16* Bhi = reinterpret_cast<__nv_bfloat16*>(smem + K4_OFF_BHI);
    __nv_bfloat16* Blo = reinterpret_cast<__nv_bfloat16*>(smem + K4_OFF_BLO);
    int l0 = blockIdx.x * 64;
    int d0 = blockIdx.y * 128;
    int b = blockIdx.z;
    int tid = threadIdx.x;
    int wid = tid >> 5;
    int wm = (wid >> 1) * 32;            // d
    int wn = (wid & 1) * 32;             // l
    float c1 = coeffs[1];

    const float4* hb4 = h4 + (((size_t)b * DM2 + d0) * SS >> 2);
#pragma unroll
    for (int k = 0; k < 8; k++) {
        int e = tid + k * 256;
        int d = e >> 4, q = e & 15;
        float4 v = hb4[e];
        v.x *= c1; v.y *= c1; v.z *= c1; v.w *= c1;
        uint2 hv, lv;
        split4(v, hv, lv);
        *reinterpret_cast<uint2*>(&Ahi[d * K4_ALD + q * 4]) = hv;
        *reinterpret_cast<uint2*>(&Alo[d * K4_ALD + q * 4]) = lv;
    }
#pragma unroll
    for (int k = 0; k < 4; k++) {
        int e = tid + k * 256;
        int si = e >> 4, q = e & 15;
        size_t src = (((size_t)b * SS + si) << 12) + l0 + q * 4;
        *reinterpret_cast<uint2*>(&Bhi[si * K4_BLD + q * 4]) =
            *reinterpret_cast<const uint2*>(&g_conv_hi[src]);
        *reinterpret_cast<uint2*>(&Blo[si * K4_BLD + q * 4]) =
            *reinterpret_cast<const uint2*>(&g_conv_lo[src]);
    }
    __syncthreads();

    wmma::fragment<wmma::accumulator, 16, 16, 16, float> acc[2][2];
#pragma unroll
    for (int i = 0; i < 2; i++)
#pragma unroll
        for (int j = 0; j < 2; j++) wmma::fill_fragment(acc[i][j], 0.f);

#pragma unroll
    for (int ks = 0; ks < 4; ks++) {
        int kk = ks * 16;
        wmma::fragment<wmma::matrix_a, 16, 16, 16, __nv_bfloat16, wmma::row_major> ah[2], al[2];
        wmma::fragment<wmma::matrix_b, 16, 16, 16, __nv_bfloat16, wmma::row_major> bh[2], bl[2];
#pragma unroll
        for (int i = 0; i < 2; i++) {
            wmma::load_matrix_sync(ah[i], Ahi + (wm + i * 16) * K4_ALD + kk, K4_ALD);
            wmma::load_matrix_sync(al[i], Alo + (wm + i * 16) * K4_ALD + kk, K4_ALD);
        }
#pragma unroll
        for (int j = 0; j < 2; j++) {
            wmma::load_matrix_sync(bh[j], Bhi + kk * K4_BLD + wn + j * 16, K4_BLD);
            wmma::load_matrix_sync(bl[j], Blo + kk * K4_BLD + wn + j * 16, K4_BLD);
        }
#pragma unroll
        for (int i = 0; i < 2; i++)
#pragma unroll
            for (int j = 0; j < 2; j++) {
                wmma::mma_sync(acc[i][j], ah[i], bh[j], acc[i][j]);
                wmma::mma_sync(acc[i][j], ah[i], bl[j], acc[i][j]);
                wmma::mma_sync(acc[i][j], al[i], bh[j], acc[i][j]);
            }
    }
    __syncthreads();
    float* stage = reinterpret_cast<float*>(smem);          // [128][72]
#pragma unroll
    for (int i = 0; i < 2; i++)
#pragma unroll
        for (int j = 0; j < 2; j++)
            wmma::store_matrix_sync(stage + (wm + i * 16) * K4_ALD + wn + j * 16,
                                    acc[i][j], K4_ALD, wmma::mem_row_major);
    __syncthreads();
#pragma unroll
    for (int k = 0; k < 8; k++) {
        int g = tid + k * 256;               // 2048 f4 = 128 rows x 16
        int row = g >> 4, c4 = g & 15;
        float4 v = *reinterpret_cast<const float4*>(&stage[row * K4_ALD + c4 * 4]);
        *reinterpret_cast<float4*>(
            &g_ypre[((size_t)b * DM2 + d0 + row) * LSZ + l0 + c4 * 4]) = v;
    }
}

// ============================================================
// k4b: final depthwise conv, float4 I/O, all 1024 channels.
// Traversal inverted for L2 reuse of g_ypre: b descending; within
// each b, ypre channels first (d descending = reverse of k4a's
// write order), then gate channels.
// ============================================================
__global__ void k4b_conv(const float* __restrict__ x,
                         const float* __restrict__ wDW,
                         const float* __restrict__ bDW,
                         float* __restrict__ out) {
    __shared__ __align__(16) float sm[66][72];
    int bx = blockIdx.x;
    int b = (BATCH - 1) - blockIdx.y;            // batches newest-first
    int c = (bx < DM2) ? (DM2 - 1 - bx)          // ypre half, d descending
                       : bx;                     // gate half 512..1023
    int tid = threadIdx.x;
    const float* plane = (c < DM2)
        ? (g_ypre + ((size_t)b * DM2 + c) * LSZ)
        : (x + ((size_t)b * DMODEL + c) * LSZ);
    const float4* plane4 = reinterpret_cast<const float4*>(plane);

    if (tid < 72) { sm[0][tid] = 0.f; sm[65][tid] = 0.f; }
    else if (tid < 136) { int r = tid - 72 + 1; sm[r][3] = 0.f; sm[r][68] = 0.f; }
#pragma unroll
    for (int k = 0; k < 4; k++) {
        int g = tid + k * 256;
        int row = g >> 4, cq = g & 15;
        *reinterpret_cast<float4*>(&sm[row + 1][4 + cq * 4]) = plane4[g];
    }
    __syncthreads();

    float w[9];
#pragma unroll
    for (int i = 0; i < 9; i++) w[i] = wDW[c * 9 + i];
    float bb = bDW[c];
    float4* ob4 = reinterpret_cast<float4*>(out + ((size_t)b * DMODEL + c) * LSZ);
#pragma unroll
    for (int k = 0; k < 4; k++) {
        int g = tid + k * 256;
        int row = g >> 4, c0 = (g & 15) * 4;
        float o[4];
#pragma unroll
        for (int u = 0; u < 4; u++) {
            int cc = c0 + u;
            float acc = bb;
#pragma unroll
            for (int i = 0; i < 3; i++)
#pragma unroll
                for (int j = 0; j < 3; j++)
                    acc += w[i * 3 + j] * sm[row + i][3 + cc + j];
            o[u] = acc;
        }
        ob4[g] = make_float4(o[0], o[1], o[2], o[3]);
    }
}

// ============================================================
extern "C" void kernel_launch(void* const* d_in, const int* in_sizes, int n_in,
                              void* d_out, int out_size) {
    const float* x      = (const float*)d_in[0];
    const float* w_bcdt = (const float*)d_in[1];
    const float* b_bcdt = (const float*)d_in[2];
    const float* w_dw   = (const float*)d_in[3];
    const float* b_dw   = (const float*)d_in[4];
    const float* A      = (const float*)d_in[5];
    const float* coeffs = (const float*)d_in[6];
    const float* w_DW   = (const float*)d_in[7];
    const float* b_DW   = (const float*)d_in[8];

    float* y_out = (float*)d_out;                          // (16,1024,4096)
    float* h_out = y_out + (size_t)BATCH * DMODEL * LSZ;   // (16,512,64)

    cudaFuncSetAttribute(k1_wmma, cudaFuncAttributeMaxDynamicSharedMemorySize, K1_SMEM);
    cudaFuncSetAttribute(k3_wmma, cudaFuncAttributeMaxDynamicSharedMemorySize, K3_SMEM);
    cudaFuncSetAttribute(k4a_wmma, cudaFuncAttributeMaxDynamicSharedMemorySize, K4_SMEM);

    cudaMemsetAsync(h_out, 0, (size_t)BATCH * DM2 * SS * sizeof(float));

    k0_convert_w<<<8, 256>>>((const float4*)w_bcdt);
    k1_wmma<<<dim3(32, 16), 256, K1_SMEM>>>((const float4*)x, b_bcdt);
    k2_conv_softmax<<<dim3(64, 16), 256>>>(w_dw, b_dw, A, coeffs);
    k3_wmma<<<dim3(8, 4, 16), 256, K3_SMEM>>>((const float4*)x, h_out);
    k4a_wmma<<<dim3(64, 4, 16), 256, K4_SMEM>>>((const float4*)h_out, coeffs);
    k4b_conv<<<dim3(1024, 16), 256>>>(x, w_DW, b_DW, y_out);
}

// round 15
// speedup vs baseline: 1.0463x; 1.0011x over previous
#include <cuda_runtime.h>
#include <cuda_bf16.h>
#include <mma.h>
#include <cstdint>

using namespace nvcuda;

#define BATCH 16
#define DMODEL 1024
#define DM2 512
#define LSZ 4096
#define SS 64

// ---- scratch (device globals; no allocations allowed) ----
__device__ float g_bcdt[BATCH * SS * LSZ];                 // 16 MB fp32
__device__ __nv_bfloat16 g_conv_hi[BATCH * SS * LSZ];      // 8 MB
__device__ __nv_bfloat16 g_conv_lo[BATCH * SS * LSZ];
__device__ __nv_bfloat16 g_AB_hi[BATCH * SS * LSZ];
__device__ __nv_bfloat16 g_AB_lo[BATCH * SS * LSZ];
__device__ __nv_bfloat16 g_w_hi[SS * DM2];
__device__ __nv_bfloat16 g_w_lo[SS * DM2];
__device__ float g_ypre[BATCH * DM2 * LSZ];                // 128 MB

// ---- side stream + fork/join events (host objects, created at load) ----
namespace {
struct StreamInit {
    cudaStream_t side;
    cudaEvent_t evFork, evJoin;
    StreamInit() {
        cudaStreamCreateWithFlags(&side, cudaStreamNonBlocking);
        cudaEventCreateWithFlags(&evFork, cudaEventDisableTiming);
        cudaEventCreateWithFlags(&evJoin, cudaEventDisableTiming);
    }
};
StreamInit g_si;
}

__device__ __forceinline__ uint32_t pk(__nv_bfloat16 a, __nv_bfloat16 b) {
    __nv_bfloat162 t; t.x = a; t.y = b;
    return *reinterpret_cast<uint32_t*>(&t);
}
__device__ __forceinline__ void split1(float v, __nv_bfloat16& hi, __nv_bfloat16& lo) {
    hi = __float2bfloat16_rn(v);
    lo = __float2bfloat16_rn(v - __bfloat162float(hi));
}
__device__ __forceinline__ void split4(float4 v, uint2& hv, uint2& lv) {
    __nv_bfloat16 h0, l0, h1, l1, h2, l2, h3, l3;
    split1(v.x, h0, l0); split1(v.y, h1, l1);
    split1(v.z, h2, l2); split1(v.w, h3, l3);
    hv = make_uint2(pk(h0, h1), pk(h2, h3));
    lv = make_uint2(pk(l0, l1), pk(l2, l3));
}

// ============================================================
// k0w: w_bcdt -> bf16 hi/lo (tiny)
// ============================================================
__global__ void k0_convert_w(const float4* __restrict__ w4) {
    int tid = threadIdx.x;
#pragma unroll
    for (int k = 0; k < 4; k++) {
        int g = blockIdx.x * 1024 + k * 256 + tid;
        uint2 hv, lv;
        split4(w4[g], hv, lv);
        *reinterpret_cast<uint2*>(&g_w_hi[g * 4]) = hv;
        *reinterpret_cast<uint2*>(&g_w_lo[g * 4]) = lv;
    }
}

// ============================================================
// k1 (wmma): BCdt[s,l] = sum_d w[s,d]*xh[d,l] + bias[s]
// ============================================================
#define K1_WLD 72
#define K1_XLD 136
#define K1_OFF_WHI 0
#define K1_OFF_WLO 9216
#define K1_OFF_XHI 18432
#define K1_OFF_XLO 35840
#define K1_SMEM 53248

__global__ void k1_wmma(const float4* __restrict__ x4, const float* __restrict__ bias) {
    extern __shared__ __align__(16) char smem[];
    __nv_bfloat16* Whi = reinterpret_cast<__nv_bfloat16*>(smem + K1_OFF_WHI);
    __nv_bfloat16* Wlo = reinterpret_cast<__nv_bfloat16*>(smem + K1_OFF_WLO);
    __nv_bfloat16* Xhi = reinterpret_cast<__nv_bfloat16*>(smem + K1_OFF_XHI);
    __nv_bfloat16* Xlo = reinterpret_cast<__nv_bfloat16*>(smem + K1_OFF_XLO);
    int b = blockIdx.y;
    int l0 = blockIdx.x * 128;
    int tid = threadIdx.x;
    int wid = tid >> 5;
    int wm = (wid >> 1) * 16;    // s
    int wn = (wid & 1) * 64;     // l

    wmma::fragment<wmma::accumulator, 16, 16, 16, float> acc[4];
#pragma unroll
    for (int j = 0; j < 4; j++) wmma::fill_fragment(acc[j], 0.f);

    for (int kc = 0; kc < DM2; kc += 64) {
#pragma unroll
        for (int k = 0; k < 4; k++) {            // W: 64s x 64k
            int e = tid + k * 256;
            int s = e >> 4, q = e & 15;
            *reinterpret_cast<uint2*>(&Whi[s * K1_WLD + q * 4]) =
                *reinterpret_cast<const uint2*>(&g_w_hi[s * DM2 + kc + q * 4]);
            *reinterpret_cast<uint2*>(&Wlo[s * K1_WLD + q * 4]) =
                *reinterpret_cast<const uint2*>(&g_w_lo[s * DM2 + kc + q * 4]);
        }
#pragma unroll
        for (int k = 0; k < 8; k++) {            // X: 64k x 128l from fp32 x
            int e = tid + k * 256;
            int r = e >> 5, q = e & 31;
            float4 v = x4[((size_t)b * DMODEL + kc + r) * 1024 + (l0 >> 2) + q];
            uint2 hv, lv;
            split4(v, hv, lv);
            *reinterpret_cast<uint2*>(&Xhi[r * K1_XLD + q * 4]) = hv;
            *reinterpret_cast<uint2*>(&Xlo[r * K1_XLD + q * 4]) = lv;
        }
        __syncthreads();
#pragma unroll
        for (int ks = 0; ks < 4; ks++) {
            int kk = ks * 16;
            wmma::fragment<wmma::matrix_a, 16, 16, 16, __nv_bfloat16, wmma::row_major> ah, al;
            wmma::load_matrix_sync(ah, Whi + wm * K1_WLD + kk, K1_WLD);
            wmma::load_matrix_sync(al, Wlo + wm * K1_WLD + kk, K1_WLD);
#pragma unroll
            for (int j = 0; j < 4; j++) {
                wmma::fragment<wmma::matrix_b, 16, 16, 16, __nv_bfloat16, wmma::row_major> bh, bl;
                wmma::load_matrix_sync(bh, Xhi + kk * K1_XLD + wn + j * 16, K1_XLD);
                wmma::load_matrix_sync(bl, Xlo + kk * K1_XLD + wn + j * 16, K1_XLD);
                wmma::mma_sync(acc[j], ah, bh, acc[j]);
                wmma::mma_sync(acc[j], ah, bl, acc[j]);
                wmma::mma_sync(acc[j], al, bh, acc[j]);
            }
        }
        __syncthreads();
    }
    float* stage = reinterpret_cast<float*>(smem);          // [64][136]
#pragma unroll
    for (int j = 0; j < 4; j++)
        wmma::store_matrix_sync(stage + wm * K1_XLD + wn + j * 16, acc[j],
                                K1_XLD, wmma::mem_row_major);
    __syncthreads();
#pragma unroll
    for (int k = 0; k < 8; k++) {
        int g = tid + k * 256;
        int row = g >> 5, c4 = g & 31;
        float bv = bias[row];
        float4 v = *reinterpret_cast<const float4*>(&stage[row * K1_XLD + c4 * 4]);
        v.x += bv; v.y += bv; v.z += bv; v.w += bv;
        *reinterpret_cast<float4*>(
            &g_bcdt[((size_t)b * SS + row) * LSZ + l0 + c4 * 4]) = v;
    }
}

// ============================================================
// k2: conv3x3 + softmax; float4 plane loads; writes bf16 hi/lo.
// ============================================================
__global__ void k2_conv_softmax(const float* __restrict__ wdw,
                                const float* __restrict__ bdw,
                                const float* __restrict__ A,
                                const float* __restrict__ coeffs) {
    __shared__ float sm[66][68];
    __shared__ float red[8];
    int s = blockIdx.x, b = blockIdx.y;
    int tid = threadIdx.x;
    size_t off = ((size_t)b * SS + s) * LSZ;
    const float4* plane4 = reinterpret_cast<const float4*>(g_bcdt + off);

    for (int e = tid; e < 66 * 68; e += 256) ((float*)sm)[e] = 0.f;
    __syncthreads();
#pragma unroll
    for (int k = 0; k < 4; k++) {
        int g = tid + k * 256;               // 1024 f4
        float4 v = plane4[g];
        int base = g * 4;
        int r = (base >> 6) + 1, c = (base & 63) + 1;
        sm[r][c] = v.x; sm[r][c + 1] = v.y; sm[r][c + 2] = v.z; sm[r][c + 3] = v.w;
    }
    __syncthreads();

    float w[9];
#pragma unroll
    for (int i = 0; i < 9; i++) w[i] = wdw[s * 9 + i];
    float bb = bdw[s];
    float c0 = coeffs[0], c2 = coeffs[2];
    float Av = A[s];

    float v[16];
    float lmax = -1e30f;
#pragma unroll
    for (int k = 0; k < 8; k++) {
        int base = tid * 2 + k * 512;
        int r = base >> 6, c = base & 63;
        float a0 = bb, a1 = bb;
#pragma unroll
        for (int i = 0; i < 3; i++)
#pragma unroll
            for (int j = 0; j < 3; j++) {
                float wv = w[i * 3 + j];
                a0 += wv * sm[r + i][c + j];
                a1 += wv * sm[r + i][c + 1 + j];
            }
        v[2 * k] = a0; v[2 * k + 1] = a1;
        lmax = fmaxf(lmax, fmaxf(c2 * a0, c2 * a1) + Av);
    }
#pragma unroll
    for (int o = 16; o > 0; o >>= 1)
        lmax = fmaxf(lmax, __shfl_xor_sync(0xffffffffu, lmax, o));
    if ((tid & 31) == 0) red[tid >> 5] = lmax;
    __syncthreads();
    float bmax = red[0];
#pragma unroll
    for (int i = 1; i < 8; i++) bmax = fmaxf(bmax, red[i]);
    __syncthreads();

    float ev[16];
    float lsum = 0.f;
#pragma unroll
    for (int k = 0; k < 16; k++) {
        ev[k] = __expf(c2 * v[k] + Av - bmax);
        lsum += ev[k];
    }
#pragma unroll
    for (int o = 16; o > 0; o >>= 1)
        lsum += __shfl_xor_sync(0xffffffffu, lsum, o);
    if ((tid & 31) == 0) red[tid >> 5] = lsum;
    __syncthreads();
    float bsum = 0.f;
#pragma unroll
    for (int i = 0; i < 8; i++) bsum += red[i];
    float inv = 1.f / bsum;

#pragma unroll
    for (int k = 0; k < 8; k++) {
        int base = tid * 2 + k * 512;
        float v0 = v[2 * k], v1 = v[2 * k + 1];
        __nv_bfloat16 ch0, cl0, ch1, cl1;
        split1(v0, ch0, cl0); split1(v1, ch1, cl1);
        *reinterpret_cast<uint32_t*>(&g_conv_hi[off + base]) = pk(ch0, ch1);
        *reinterpret_cast<uint32_t*>(&g_conv_lo[off + base]) = pk(cl0, cl1);
        float a0 = ev[2 * k] * inv * c0 * v0;
        float a1 = ev[2 * k + 1] * inv * c0 * v1;
        __nv_bfloat16 ah0, al0, ah1, al1;
        split1(a0, ah0, al0); split1(a1, ah1, al1);
        *reinterpret_cast<uint32_t*>(&g_AB_hi[off + base]) = pk(ah0, ah1);
        *reinterpret_cast<uint32_t*>(&g_AB_lo[off + base]) = pk(al0, al1);
    }
}

// ============================================================
// k3 (wmma): h[d,s] = sum_l xh[d,l]*AB[s,l]; L-split 8, atomics.
// ============================================================
#define K3_ALD 72
#define K3_BLD 72
#define K3_OFF_AHI 0
#define K3_OFF_ALO 18432
#define K3_OFF_BHI 36864
#define K3_OFF_BLO 46080
#define K3_SMEM 55296

__global__ void k3_wmma(const float4* __restrict__ x4, float* __restrict__ hout) {
    extern __shared__ __align__(16) char smem[];
    __nv_bfloat16* Ahi = reinterpret_cast<__nv_bfloat16*>(smem + K3_OFF_AHI);
    __nv_bfloat16* Alo = reinterpret_cast<__nv_bfloat16*>(smem + K3_OFF_ALO);
    __nv_bfloat16* Bhi = reinterpret_cast<__nv_bfloat16*>(smem + K3_OFF_BHI);
    __nv_bfloat16* Blo = reinterpret_cast<__nv_bfloat16*>(smem + K3_OFF_BLO);
    int lp = blockIdx.x;                 // 0..7
    int d0 = blockIdx.y * 128;
    int b = blockIdx.z;
    int tid = threadIdx.x;
    int wid = tid >> 5;
    int wm = (wid >> 1) * 32;            // d
    int wn = (wid & 1) * 32;             // s

    wmma::fragment<wmma::accumulator, 16, 16, 16, float> acc[2][2];
#pragma unroll
    for (int i = 0; i < 2; i++)
#pragma unroll
        for (int j = 0; j < 2; j++) wmma::fill_fragment(acc[i][j], 0.f);

    for (int lc = 0; lc < 512; lc += 64) {
        int lbase = lp * 512 + lc;
#pragma unroll
        for (int k = 0; k < 8; k++) {        // A: 128d x 64l from fp32 x
            int e = tid + k * 256;
            int d = e >> 4, q = e & 15;
            float4 v = x4[((size_t)b * DMODEL + d0 + d) * 1024 + (lbase >> 2) + q];
            uint2 hv, lv;
            split4(v, hv, lv);
            *reinterpret_cast<uint2*>(&Ahi[d * K3_ALD + q * 4]) = hv;
            *reinterpret_cast<uint2*>(&Alo[d * K3_ALD + q * 4]) = lv;
        }
#pragma unroll
        for (int k = 0; k < 4; k++) {        // B: 64s x 64l
            int e = tid + k * 256;
            int si = e >> 4, q = e & 15;
            size_t src = (((size_t)b * SS + si) << 12) + lbase + q * 4;
            *reinterpret_cast<uint2*>(&Bhi[si * K3_BLD + q * 4]) =
                *reinterpret_cast<const uint2*>(&g_AB_hi[src]);
            *reinterpret_cast<uint2*>(&Blo[si * K3_BLD + q * 4]) =
                *reinterpret_cast<const uint2*>(&g_AB_lo[src]);
        }
        __syncthreads();
#pragma unroll
        for (int ks = 0; ks < 4; ks++) {
            int kk = ks * 16;
            wmma::fragment<wmma::matrix_a, 16, 16, 16, __nv_bfloat16, wmma::row_major> ah[2], al[2];
            wmma::fragment<wmma::matrix_b, 16, 16, 16, __nv_bfloat16, wmma::col_major> bh[2], bl[2];
#pragma unroll
            for (int i = 0; i < 2; i++) {
                wmma::load_matrix_sync(ah[i], Ahi + (wm + i * 16) * K3_ALD + kk, K3_ALD);
                wmma::load_matrix_sync(al[i], Alo + (wm + i * 16) * K3_ALD + kk, K3_ALD);
            }
#pragma unroll
            for (int j = 0; j < 2; j++) {
                wmma::load_matrix_sync(bh[j], Bhi + (wn + j * 16) * K3_BLD + kk, K3_BLD);
                wmma::load_matrix_sync(bl[j], Blo + (wn + j * 16) * K3_BLD + kk, K3_BLD);
            }
#pragma unroll
            for (int i = 0; i < 2; i++)
#pragma unroll
                for (int j = 0; j < 2; j++) {
                    wmma::mma_sync(acc[i][j], ah[i], bh[j], acc[i][j]);
                    wmma::mma_sync(acc[i][j], ah[i], bl[j], acc[i][j]);
                    wmma::mma_sync(acc[i][j], al[i], bh[j], acc[i][j]);
                }
        }
        __syncthreads();
    }
    float* stage = reinterpret_cast<float*>(smem);          // [128][72]
#pragma unroll
    for (int i = 0; i < 2; i++)
#pragma unroll
        for (int j = 0; j < 2; j++)
            wmma::store_matrix_sync(stage + (wm + i * 16) * K3_ALD + wn + j * 16,
                                    acc[i][j], K3_ALD, wmma::mem_row_major);
    __syncthreads();
    float* hb = hout + ((size_t)b * DM2 + d0) * SS;
#pragma unroll
    for (int k = 0; k < 32; k++) {
        int e = tid + k * 256;
        int d = e >> 6, si = e & 63;
        atomicAdd(&hb[d * SS + si], stage[d * K3_ALD + si]);
    }
}

// ============================================================
// k4a (wmma): y_pre[d,l] = sum_s (c1*h)[d,s]*conv[s,l]
// ============================================================
#define K4_ALD 72
#define K4_BLD 72
#define K4_OFF_AHI 0
#define K4_OFF_ALO 18432
#define K4_OFF_BHI 36864
#define K4_OFF_BLO 46080
#define K4_SMEM 55296

__global__ void k4a_wmma(const float4* __restrict__ h4,
                         const float* __restrict__ coeffs) {
    extern __shared__ __align__(16) char smem[];
    __nv_bfloat16* Ahi = reinterpret_cast<__nv_bfloat16*>(smem + K4_OFF_AHI);
    __nv_bfloat16* Alo = reinterpret_cast<__nv_bfloat16*>(smem + K4_OFF_ALO);
    __nv_bfloat16* Bhi = reinterpret_cast<__nv_bfloat16*>(smem + K4_OFF_BHI);
    __nv_bfloat16* Blo = reinterpret_cast<__nv_bfloat16*>(smem + K4_OFF_BLO);
    int l0 = blockIdx.x * 64;
    int d0 = blockIdx.y * 128;
    int b = blockIdx.z;
    int tid = threadIdx.x;
    int wid = tid >> 5;
    int wm = (wid >> 1) * 32;            // d
    int wn = (wid & 1) * 32;             // l
    float c1 = coeffs[1];

    const float4* hb4 = h4 + (((size_t)b * DM2 + d0) * SS >> 2);
#pragma unroll
    for (int k = 0; k < 8; k++) {
        int e = tid + k * 256;
        int d = e >> 4, q = e & 15;
        float4 v = hb4[e];
        v.x *= c1; v.y *= c1; v.z *= c1; v.w *= c1;
        uint2 hv, lv;
        split4(v, hv, lv);
        *reinterpret_cast<uint2*>(&Ahi[d * K4_ALD + q * 4]) = hv;
        *reinterpret_cast<uint2*>(&Alo[d * K4_ALD + q * 4]) = lv;
    }
#pragma unroll
    for (int k = 0; k < 4; k++) {
        int e = tid + k * 256;
        int si = e >> 4, q = e & 15;
        size_t src = (((size_t)b * SS + si) << 12) + l0 + q * 4;
        *reinterpret_cast<uint2*>(&Bhi[si * K4_BLD + q * 4]) =
            *reinterpret_cast<const uint2*>(&g_conv_hi[src]);
        *reinterpret_cast<uint2*>(&Blo[si * K4_BLD + q * 4]) =
            *reinterpret_cast<const uint2*>(&g_conv_lo[src]);
    }
    __syncthreads();

    wmma::fragment<wmma::accumulator, 16, 16, 16, float> acc[2][2];
#pragma unroll
    for (int i = 0; i < 2; i++)
#pragma unroll
        for (int j = 0; j < 2; j++) wmma::fill_fragment(acc[i][j], 0.f);

#pragma unroll
    for (int ks = 0; ks < 4; ks++) {
        int kk = ks * 16;
        wmma::fragment<wmma::matrix_a, 16, 16, 16, __nv_bfloat16, wmma::row_major> ah[2], al[2];
        wmma::fragment<wmma::matrix_b, 16, 16, 16, __nv_bfloat16, wmma::row_major> bh[2], bl[2];
#pragma unroll
        for (int i = 0; i < 2; i++) {
            wmma::load_matrix_sync(ah[i], Ahi + (wm + i * 16) * K4_ALD + kk, K4_ALD);
            wmma::load_matrix_sync(al[i], Alo + (wm + i * 16) * K4_ALD + kk, K4_ALD);
        }
#pragma unroll
        for (int j = 0; j < 2; j++) {
            wmma::load_matrix_sync(bh[j], Bhi + kk * K4_BLD + wn + j * 16, K4_BLD);
            wmma::load_matrix_sync(bl[j], Blo + kk * K4_BLD + wn + j * 16, K4_BLD);
        }
#pragma unroll
        for (int i = 0; i < 2; i++)
#pragma unroll
            for (int j = 0; j < 2; j++) {
                wmma::mma_sync(acc[i][j], ah[i], bh[j], acc[i][j]);
                wmma::mma_sync(acc[i][j], ah[i], bl[j], acc[i][j]);
                wmma::mma_sync(acc[i][j], al[i], bh[j], acc[i][j]);
            }
    }
    __syncthreads();
    float* stage = reinterpret_cast<float*>(smem);          // [128][72]
#pragma unroll
    for (int i = 0; i < 2; i++)
#pragma unroll
        for (int j = 0; j < 2; j++)
            wmma::store_matrix_sync(stage + (wm + i * 16) * K4_ALD + wn + j * 16,
                                    acc[i][j], K4_ALD, wmma::mem_row_major);
    __syncthreads();
#pragma unroll
    for (int k = 0; k < 8; k++) {
        int g = tid + k * 256;               // 2048 f4 = 128 rows x 16
        int row = g >> 4, c4 = g & 15;
        float4 v = *reinterpret_cast<const float4*>(&stage[row * K4_ALD + c4 * 4]);
        *reinterpret_cast<float4*>(
            &g_ypre[((size_t)b * DM2 + d0 + row) * LSZ + l0 + c4 * 4]) = v;
    }
}

// ============================================================
// shared conv body for k4b halves
// ============================================================
__device__ __forceinline__ void dwconv_plane(const float* __restrict__ plane,
                                             const float* __restrict__ wDW,
                                             const float* __restrict__ bDW,
                                             int c, int b,
                                             float* __restrict__ out,
                                             float sm[66][72]) {
    int tid = threadIdx.x;
    const float4* plane4 = reinterpret_cast<const float4*>(plane);
    if (tid < 72) { sm[0][tid] = 0.f; sm[65][tid] = 0.f; }
    else if (tid < 136) { int r = tid - 72 + 1; sm[r][3] = 0.f; sm[r][68] = 0.f; }
#pragma unroll
    for (int k = 0; k < 4; k++) {
        int g = tid + k * 256;
        int row = g >> 4, cq = g & 15;
        *reinterpret_cast<float4*>(&sm[row + 1][4 + cq * 4]) = plane4[g];
    }
    __syncthreads();

    float w[9];
#pragma unroll
    for (int i = 0; i < 9; i++) w[i] = wDW[c * 9 + i];
    float bb = bDW[c];
    float4* ob4 = reinterpret_cast<float4*>(out + ((size_t)b * DMODEL + c) * LSZ);
#pragma unroll
    for (int k = 0; k < 4; k++) {
        int g = tid + k * 256;
        int row = g >> 4, c0 = (g & 15) * 4;
        float o[4];
#pragma unroll
        for (int u = 0; u < 4; u++) {
            int cc = c0 + u;
            float acc = bb;
#pragma unroll
            for (int i = 0; i < 3; i++)
#pragma unroll
                for (int j = 0; j < 3; j++)
                    acc += w[i * 3 + j] * sm[row + i][3 + cc + j];
            o[u] = acc;
        }
        ob4[g] = make_float4(o[0], o[1], o[2], o[3]);
    }
}

// k4b ypre half: channels 0..511, read most-recent k4a output first.
__global__ void k4b_ypre(const float* __restrict__ wDW,
                         const float* __restrict__ bDW,
                         float* __restrict__ out) {
    __shared__ __align__(16) float sm[66][72];
    int b = (BATCH - 1) - blockIdx.y;
    int c = (DM2 - 1) - blockIdx.x;      // d descending (reverse of write order)
    dwconv_plane(g_ypre + ((size_t)b * DM2 + c) * LSZ, wDW, bDW, c, b, out, sm);
}

// k4b gate half: channels 512..1023, depends only on x. Runs on side stream.
__global__ void k4b_gate(const float* __restrict__ x,
                         const float* __restrict__ wDW,
                         const float* __restrict__ bDW,
                         float* __restrict__ out) {
    __shared__ __align__(16) float sm[66][72];
    int b = blockIdx.y;
    int c = DM2 + blockIdx.x;
    dwconv_plane(x + ((size_t)b * DMODEL + c) * LSZ, wDW, bDW, c, b, out, sm);
}

// ============================================================
extern "C" void kernel_launch(void* const* d_in, const int* in_sizes, int n_in,
                              void* d_out, int out_size) {
    const float* x      = (const float*)d_in[0];
    const float* w_bcdt = (const float*)d_in[1];
    const float* b_bcdt = (const float*)d_in[2];
    const float* w_dw   = (const float*)d_in[3];
    const float* b_dw   = (const float*)d_in[4];
    const float* A      = (const float*)d_in[5];
    const float* coeffs = (const float*)d_in[6];
    const float* w_DW   = (const float*)d_in[7];
    const float* b_DW   = (const float*)d_in[8];

    float* y_out = (float*)d_out;                          // (16,1024,4096)
    float* h_out = y_out + (size_t)BATCH * DMODEL * LSZ;   // (16,512,64)

    cudaFuncSetAttribute(k1_wmma, cudaFuncAttributeMaxDynamicSharedMemorySize, K1_SMEM);
    cudaFuncSetAttribute(k3_wmma, cudaFuncAttributeMaxDynamicSharedMemorySize, K3_SMEM);
    cudaFuncSetAttribute(k4a_wmma, cudaFuncAttributeMaxDynamicSharedMemorySize, K4_SMEM);

    // ---- fork: gate conv (depends only on x) runs on side stream ----
    cudaEventRecord(g_si.evFork, 0);
    cudaStreamWaitEvent(g_si.side, g_si.evFork, 0);
    k4b_gate<<<dim3(DM2, BATCH), 256, 0, g_si.side>>>(x, w_DW, b_DW, y_out);
    cudaEventRecord(g_si.evJoin, g_si.side);

    // ---- main pipeline ----
    cudaMemsetAsync(h_out, 0, (size_t)BATCH * DM2 * SS * sizeof(float));
    k0_convert_w<<<8, 256>>>((const float4*)w_bcdt);
    k1_wmma<<<dim3(32, 16), 256, K1_SMEM>>>((const float4*)x, b_bcdt);
    k2_conv_softmax<<<dim3(64, 16), 256>>>(w_dw, b_dw, A, coeffs);
    k3_wmma<<<dim3(8, 4, 16), 256, K3_SMEM>>>((const float4*)x, h_out);
    k4a_wmma<<<dim3(64, 4, 16), 256, K4_SMEM>>>((const float4*)h_out, coeffs);
    k4b_ypre<<<dim3(DM2, BATCH), 256>>>(w_DW, b_DW, y_out);

    // ---- join ----
    cudaStreamWaitEvent(0, g_si.evJoin, 0);
}

// round 16
// speedup vs baseline: 1.0796x; 1.0318x over previous
#include <cuda_runtime.h>
#include <cuda_bf16.h>
#include <cuda_fp16.h>
#include <mma.h>
#include <cstdint>

using namespace nvcuda;

#define BATCH 16
#define DMODEL 1024
#define DM2 512
#define LSZ 4096
#define SS 64

// ---- scratch (device globals; no allocations allowed) ----
__device__ float g_bcdt[BATCH * SS * LSZ];                 // 16 MB fp32
__device__ __nv_bfloat16 g_conv_hi[BATCH * SS * LSZ];      // 8 MB
__device__ __nv_bfloat16 g_conv_lo[BATCH * SS * LSZ];
__device__ __nv_bfloat16 g_AB_hi[BATCH * SS * LSZ];
__device__ __nv_bfloat16 g_AB_lo[BATCH * SS * LSZ];
__device__ __nv_bfloat16 g_w_hi[SS * DM2];
__device__ __nv_bfloat16 g_w_lo[SS * DM2];
__device__ __half g_ypre[BATCH * DM2 * LSZ];               // 64 MB fp16

// ---- side stream + fork/join events (host objects, created at load) ----
namespace {
struct StreamInit {
    cudaStream_t side;
    cudaEvent_t evFork, evJoin;
    StreamInit() {
        cudaStreamCreateWithFlags(&side, cudaStreamNonBlocking);
        cudaEventCreateWithFlags(&evFork, cudaEventDisableTiming);
        cudaEventCreateWithFlags(&evJoin, cudaEventDisableTiming);
    }
};
StreamInit g_si;
}

__device__ __forceinline__ uint32_t pk(__nv_bfloat16 a, __nv_bfloat16 b) {
    __nv_bfloat162 t; t.x = a; t.y = b;
    return *reinterpret_cast<uint32_t*>(&t);
}
__device__ __forceinline__ void split1(float v, __nv_bfloat16& hi, __nv_bfloat16& lo) {
    hi = __float2bfloat16_rn(v);
    lo = __float2bfloat16_rn(v - __bfloat162float(hi));
}
__device__ __forceinline__ void split4(float4 v, uint2& hv, uint2& lv) {
    __nv_bfloat16 h0, l0, h1, l1, h2, l2, h3, l3;
    split1(v.x, h0, l0); split1(v.y, h1, l1);
    split1(v.z, h2, l2); split1(v.w, h3, l3);
    hv = make_uint2(pk(h0, h1), pk(h2, h3));
    lv = make_uint2(pk(l0, l1), pk(l2, l3));
}

// ============================================================
// k0w: w_bcdt -> bf16 hi/lo (tiny)
// ============================================================
__global__ void k0_convert_w(const float4* __restrict__ w4) {
    int tid = threadIdx.x;
#pragma unroll
    for (int k = 0; k < 4; k++) {
        int g = blockIdx.x * 1024 + k * 256 + tid;
        uint2 hv, lv;
        split4(w4[g], hv, lv);
        *reinterpret_cast<uint2*>(&g_w_hi[g * 4]) = hv;
        *reinterpret_cast<uint2*>(&g_w_lo[g * 4]) = lv;
    }
}

// ============================================================
// k1 (wmma): BCdt[s,l] = sum_d w[s,d]*xh[d,l] + bias[s]
// ============================================================
#define K1_WLD 72
#define K1_XLD 136
#define K1_OFF_WHI 0
#define K1_OFF_WLO 9216
#define K1_OFF_XHI 18432
#define K1_OFF_XLO 35840
#define K1_SMEM 53248

__global__ void k1_wmma(const float4* __restrict__ x4, const float* __restrict__ bias) {
    extern __shared__ __align__(16) char smem[];
    __nv_bfloat16* Whi = reinterpret_cast<__nv_bfloat16*>(smem + K1_OFF_WHI);
    __nv_bfloat16* Wlo = reinterpret_cast<__nv_bfloat16*>(smem + K1_OFF_WLO);
    __nv_bfloat16* Xhi = reinterpret_cast<__nv_bfloat16*>(smem + K1_OFF_XHI);
    __nv_bfloat16* Xlo = reinterpret_cast<__nv_bfloat16*>(smem + K1_OFF_XLO);
    int b = blockIdx.y;
    int l0 = blockIdx.x * 128;
    int tid = threadIdx.x;
    int wid = tid >> 5;
    int wm = (wid >> 1) * 16;    // s
    int wn = (wid & 1) * 64;     // l

    wmma::fragment<wmma::accumulator, 16, 16, 16, float> acc[4];
#pragma unroll
    for (int j = 0; j < 4; j++) wmma::fill_fragment(acc[j], 0.f);

    for (int kc = 0; kc < DM2; kc += 64) {
#pragma unroll
        for (int k = 0; k < 4; k++) {            // W: 64s x 64k
            int e = tid + k * 256;
            int s = e >> 4, q = e & 15;
            *reinterpret_cast<uint2*>(&Whi[s * K1_WLD + q * 4]) =
                *reinterpret_cast<const uint2*>(&g_w_hi[s * DM2 + kc + q * 4]);
            *reinterpret_cast<uint2*>(&Wlo[s * K1_WLD + q * 4]) =
                *reinterpret_cast<const uint2*>(&g_w_lo[s * DM2 + kc + q * 4]);
        }
#pragma unroll
        for (int k = 0; k < 8; k++) {            // X: 64k x 128l from fp32 x
            int e = tid + k * 256;
            int r = e >> 5, q = e & 31;
            float4 v = x4[((size_t)b * DMODEL + kc + r) * 1024 + (l0 >> 2) + q];
            uint2 hv, lv;
            split4(v, hv, lv);
            *reinterpret_cast<uint2*>(&Xhi[r * K1_XLD + q * 4]) = hv;
            *reinterpret_cast<uint2*>(&Xlo[r * K1_XLD + q * 4]) = lv;
        }
        __syncthreads();
#pragma unroll
        for (int ks = 0; ks < 4; ks++) {
            int kk = ks * 16;
            wmma::fragment<wmma::matrix_a, 16, 16, 16, __nv_bfloat16, wmma::row_major> ah, al;
            wmma::load_matrix_sync(ah, Whi + wm * K1_WLD + kk, K1_WLD);
            wmma::load_matrix_sync(al, Wlo + wm * K1_WLD + kk, K1_WLD);
#pragma unroll
            for (int j = 0; j < 4; j++) {
                wmma::fragment<wmma::matrix_b, 16, 16, 16, __nv_bfloat16, wmma::row_major> bh, bl;
                wmma::load_matrix_sync(bh, Xhi + kk * K1_XLD + wn + j * 16, K1_XLD);
                wmma::load_matrix_sync(bl, Xlo + kk * K1_XLD + wn + j * 16, K1_XLD);
                wmma::mma_sync(acc[j], ah, bh, acc[j]);
                wmma::mma_sync(acc[j], ah, bl, acc[j]);
                wmma::mma_sync(acc[j], al, bh, acc[j]);
            }
        }
        __syncthreads();
    }
    float* stage = reinterpret_cast<float*>(smem);          // [64][136]
#pragma unroll
    for (int j = 0; j < 4; j++)
        wmma::store_matrix_sync(stage + wm * K1_XLD + wn + j * 16, acc[j],
                                K1_XLD, wmma::mem_row_major);
    __syncthreads();
#pragma unroll
    for (int k = 0; k < 8; k++) {
        int g = tid + k * 256;
        int row = g >> 5, c4 = g & 31;
        float bv = bias[row];
        float4 v = *reinterpret_cast<const float4*>(&stage[row * K1_XLD + c4 * 4]);
        v.x += bv; v.y += bv; v.z += bv; v.w += bv;
        *reinterpret_cast<float4*>(
            &g_bcdt[((size_t)b * SS + row) * LSZ + l0 + c4 * 4]) = v;
    }
}

// ============================================================
// k2: conv3x3 + softmax; float4 plane loads; writes bf16 hi/lo.
// ============================================================
__global__ void k2_conv_softmax(const float* __restrict__ wdw,
                                const float* __restrict__ bdw,
                                const float* __restrict__ A,
                                const float* __restrict__ coeffs) {
    __shared__ float sm[66][68];
    __shared__ float red[8];
    int s = blockIdx.x, b = blockIdx.y;
    int tid = threadIdx.x;
    size_t off = ((size_t)b * SS + s) * LSZ;
    const float4* plane4 = reinterpret_cast<const float4*>(g_bcdt + off);

    for (int e = tid; e < 66 * 68; e += 256) ((float*)sm)[e] = 0.f;
    __syncthreads();
#pragma unroll
    for (int k = 0; k < 4; k++) {
        int g = tid + k * 256;               // 1024 f4
        float4 v = plane4[g];
        int base = g * 4;
        int r = (base >> 6) + 1, c = (base & 63) + 1;
        sm[r][c] = v.x; sm[r][c + 1] = v.y; sm[r][c + 2] = v.z; sm[r][c + 3] = v.w;
    }
    __syncthreads();

    float w[9];
#pragma unroll
    for (int i = 0; i < 9; i++) w[i] = wdw[s * 9 + i];
    float bb = bdw[s];
    float c0 = coeffs[0], c2 = coeffs[2];
    float Av = A[s];

    float v[16];
    float lmax = -1e30f;
#pragma unroll
    for (int k = 0; k < 8; k++) {
        int base = tid * 2 + k * 512;
        int r = base >> 6, c = base & 63;
        float a0 = bb, a1 = bb;
#pragma unroll
        for (int i = 0; i < 3; i++)
#pragma unroll
            for (int j = 0; j < 3; j++) {
                float wv = w[i * 3 + j];
                a0 += wv * sm[r + i][c + j];
                a1 += wv * sm[r + i][c + 1 + j];
            }
        v[2 * k] = a0; v[2 * k + 1] = a1;
        lmax = fmaxf(lmax, fmaxf(c2 * a0, c2 * a1) + Av);
    }
#pragma unroll
    for (int o = 16; o > 0; o >>= 1)
        lmax = fmaxf(lmax, __shfl_xor_sync(0xffffffffu, lmax, o));
    if ((tid & 31) == 0) red[tid >> 5] = lmax;
    __syncthreads();
    float bmax = red[0];
#pragma unroll
    for (int i = 1; i < 8; i++) bmax = fmaxf(bmax, red[i]);
    __syncthreads();

    float ev[16];
    float lsum = 0.f;
#pragma unroll
    for (int k = 0; k < 16; k++) {
        ev[k] = __expf(c2 * v[k] + Av - bmax);
        lsum += ev[k];
    }
#pragma unroll
    for (int o = 16; o > 0; o >>= 1)
        lsum += __shfl_xor_sync(0xffffffffu, lsum, o);
    if ((tid & 31) == 0) red[tid >> 5] = lsum;
    __syncthreads();
    float bsum = 0.f;
#pragma unroll
    for (int i = 0; i < 8; i++) bsum += red[i];
    float inv = 1.f / bsum;

#pragma unroll
    for (int k = 0; k < 8; k++) {
        int base = tid * 2 + k * 512;
        float v0 = v[2 * k], v1 = v[2 * k + 1];
        __nv_bfloat16 ch0, cl0, ch1, cl1;
        split1(v0, ch0, cl0); split1(v1, ch1, cl1);
        *reinterpret_cast<uint32_t*>(&g_conv_hi[off + base]) = pk(ch0, ch1);
        *reinterpret_cast<uint32_t*>(&g_conv_lo[off + base]) = pk(cl0, cl1);
        float a0 = ev[2 * k] * inv * c0 * v0;
        float a1 = ev[2 * k + 1] * inv * c0 * v1;
        __nv_bfloat16 ah0, al0, ah1, al1;
        split1(a0, ah0, al0); split1(a1, ah1, al1);
        *reinterpret_cast<uint32_t*>(&g_AB_hi[off + base]) = pk(ah0, ah1);
        *reinterpret_cast<uint32_t*>(&g_AB_lo[off + base]) = pk(al0, al1);
    }
}

// ============================================================
// k3 (wmma): h[d,s] = sum_l xh[d,l]*AB[s,l]; L-split 8, atomics.
// ============================================================
#define K3_ALD 72
#define K3_BLD 72
#define K3_OFF_AHI 0
#define K3_OFF_ALO 18432
#define K3_OFF_BHI 36864
#define K3_OFF_BLO 46080
#define K3_SMEM 55296

__global__ void k3_wmma(const float4* __restrict__ x4, float* __restrict__ hout) {
    extern __shared__ __align__(16) char smem[];
    __nv_bfloat16* Ahi = reinterpret_cast<__nv_bfloat16*>(smem + K3_OFF_AHI);
    __nv_bfloat16* Alo = reinterpret_cast<__nv_bfloat16*>(smem + K3_OFF_ALO);
    __nv_bfloat16* Bhi = reinterpret_cast<__nv_bfloat16*>(smem + K3_OFF_BHI);
    __nv_bfloat16* Blo = reinterpret_cast<__nv_bfloat16*>(smem + K3_OFF_BLO);
    int lp = blockIdx.x;                 // 0..7
    int d0 = blockIdx.y * 128;
    int b = blockIdx.z;
    int tid = threadIdx.x;
    int wid = tid >> 5;
    int wm = (wid >> 1) * 32;            // d
    int wn = (wid & 1) * 32;             // s

    wmma::fragment<wmma::accumulator, 16, 16, 16, float> acc[2][2];
#pragma unroll
    for (int i = 0; i < 2; i++)
#pragma unroll
        for (int j = 0; j < 2; j++) wmma::fill_fragment(acc[i][j], 0.f);

    for (int lc = 0; lc < 512; lc += 64) {
        int lbase = lp * 512 + lc;
#pragma unroll
        for (int k = 0; k < 8; k++) {        // A: 128d x 64l from fp32 x
            int e = tid + k * 256;
            int d = e >> 4, q = e & 15;
            float4 v = x4[((size_t)b * DMODEL + d0 + d) * 1024 + (lbase >> 2) + q];
            uint2 hv, lv;
            split4(v, hv, lv);
            *reinterpret_cast<uint2*>(&Ahi[d * K3_ALD + q * 4]) = hv;
            *reinterpret_cast<uint2*>(&Alo[d * K3_ALD + q * 4]) = lv;
        }
#pragma unroll
        for (int k = 0; k < 4; k++) {        // B: 64s x 64l
            int e = tid + k * 256;
            int si = e >> 4, q = e & 15;
            size_t src = (((size_t)b * SS + si) << 12) + lbase + q * 4;
            *reinterpret_cast<uint2*>(&Bhi[si * K3_BLD + q * 4]) =
                *reinterpret_cast<const uint2*>(&g_AB_hi[src]);
            *reinterpret_cast<uint2*>(&Blo[si * K3_BLD + q * 4]) =
                *reinterpret_cast<const uint2*>(&g_AB_lo[src]);
        }
        __syncthreads();
#pragma unroll
        for (int ks = 0; ks < 4; ks++) {
            int kk = ks * 16;
            wmma::fragment<wmma::matrix_a, 16, 16, 16, __nv_bfloat16, wmma::row_major> ah[2], al[2];
            wmma::fragment<wmma::matrix_b, 16, 16, 16, __nv_bfloat16, wmma::col_major> bh[2], bl[2];
#pragma unroll
            for (int i = 0; i < 2; i++) {
                wmma::load_matrix_sync(ah[i], Ahi + (wm + i * 16) * K3_ALD + kk, K3_ALD);
                wmma::load_matrix_sync(al[i], Alo + (wm + i * 16) * K3_ALD + kk, K3_ALD);
            }
#pragma unroll
            for (int j = 0; j < 2; j++) {
                wmma::load_matrix_sync(bh[j], Bhi + (wn + j * 16) * K3_BLD + kk, K3_BLD);
                wmma::load_matrix_sync(bl[j], Blo + (wn + j * 16) * K3_BLD + kk, K3_BLD);
            }
#pragma unroll
            for (int i = 0; i < 2; i++)
#pragma unroll
                for (int j = 0; j < 2; j++) {
                    wmma::mma_sync(acc[i][j], ah[i], bh[j], acc[i][j]);
                    wmma::mma_sync(acc[i][j], ah[i], bl[j], acc[i][j]);
                    wmma::mma_sync(acc[i][j], al[i], bh[j], acc[i][j]);
                }
        }
        __syncthreads();
    }
    float* stage = reinterpret_cast<float*>(smem);          // [128][72]
#pragma unroll
    for (int i = 0; i < 2; i++)
#pragma unroll
        for (int j = 0; j < 2; j++)
            wmma::store_matrix_sync(stage + (wm + i * 16) * K3_ALD + wn + j * 16,
                                    acc[i][j], K3_ALD, wmma::mem_row_major);
    __syncthreads();
    float* hb = hout + ((size_t)b * DM2 + d0) * SS;
#pragma unroll
    for (int k = 0; k < 32; k++) {
        int e = tid + k * 256;
        int d = e >> 6, si = e & 63;
        atomicAdd(&hb[d * SS + si], stage[d * K3_ALD + si]);
    }
}

// ============================================================
// k4a (wmma): y_pre[d,l] = sum_s (c1*h)[d,s]*conv[s,l]; fp16 out.
// ============================================================
#define K4_ALD 72
#define K4_BLD 72
#define K4_OFF_AHI 0
#define K4_OFF_ALO 18432
#define K4_OFF_BHI 36864
#define K4_OFF_BLO 46080
#define K4_SMEM 55296

__global__ void k4a_wmma(const float4* __restrict__ h4,
                         const float* __restrict__ coeffs) {
    extern __shared__ __align__(16) char smem[];
    __nv_bfloat16* Ahi = reinterpret_cast<__nv_bfloat16*>(smem + K4_OFF_AHI);
    __nv_bfloat16* Alo = reinterpret_cast<__nv_bfloat16*>(smem + K4_OFF_ALO);
    __nv_bfloat16* Bhi = reinterpret_cast<__nv_bfloat16*>(smem + K4_OFF_BHI);
    __nv_bfloat16* Blo = reinterpret_cast<__nv_bfloat16*>(smem + K4_OFF_BLO);
    int l0 = blockIdx.x * 64;
    int d0 = blockIdx.y * 128;
    int b = blockIdx.z;
    int tid = threadIdx.x;
    int wid = tid >> 5;
    int wm = (wid >> 1) * 32;            // d
    int wn = (wid & 1) * 32;             // l
    float c1 = coeffs[1];

    const float4* hb4 = h4 + (((size_t)b * DM2 + d0) * SS >> 2);
#pragma unroll
    for (int k = 0; k < 8; k++) {
        int e = tid + k * 256;
        int d = e >> 4, q = e & 15;
        float4 v = hb4[e];
        v.x *= c1; v.y *= c1; v.z *= c1; v.w *= c1;
        uint2 hv, lv;
        split4(v, hv, lv);
        *reinterpret_cast<uint2*>(&Ahi[d * K4_ALD + q * 4]) = hv;
        *reinterpret_cast<uint2*>(&Alo[d * K4_ALD + q * 4]) = lv;
    }
#pragma unroll
    for (int k = 0; k < 4; k++) {
        int e = tid + k * 256;
        int si = e >> 4, q = e & 15;
        size_t src = (((size_t)b * SS + si) << 12) + l0 + q * 4;
        *reinterpret_cast<uint2*>(&Bhi[si * K4_BLD + q * 4]) =
            *reinterpret_cast<const uint2*>(&g_conv_hi[src]);
        *reinterpret_cast<uint2*>(&Blo[si * K4_BLD + q * 4]) =
            *reinterpret_cast<const uint2*>(&g_conv_lo[src]);
    }
    __syncthreads();

    wmma::fragment<wmma::accumulator, 16, 16, 16, float> acc[2][2];
#pragma unroll
    for (int i = 0; i < 2; i++)
#pragma unroll
        for (int j = 0; j < 2; j++) wmma::fill_fragment(acc[i][j], 0.f);

#pragma unroll
    for (int ks = 0; ks < 4; ks++) {
        int kk = ks * 16;
        wmma::fragment<wmma::matrix_a, 16, 16, 16, __nv_bfloat16, wmma::row_major> ah[2], al[2];
        wmma::fragment<wmma::matrix_b, 16, 16, 16, __nv_bfloat16, wmma::row_major> bh[2], bl[2];
#pragma unroll
        for (int i = 0; i < 2; i++) {
            wmma::load_matrix_sync(ah[i], Ahi + (wm + i * 16) * K4_ALD + kk, K4_ALD);
            wmma::load_matrix_sync(al[i], Alo + (wm + i * 16) * K4_ALD + kk, K4_ALD);
        }
#pragma unroll
        for (int j = 0; j < 2; j++) {
            wmma::load_matrix_sync(bh[j], Bhi + kk * K4_BLD + wn + j * 16, K4_BLD);
            wmma::load_matrix_sync(bl[j], Blo + kk * K4_BLD + wn + j * 16, K4_BLD);
        }
#pragma unroll
        for (int i = 0; i < 2; i++)
#pragma unroll
            for (int j = 0; j < 2; j++) {
                wmma::mma_sync(acc[i][j], ah[i], bh[j], acc[i][j]);
                wmma::mma_sync(acc[i][j], ah[i], bl[j], acc[i][j]);
                wmma::mma_sync(acc[i][j], al[i], bh[j], acc[i][j]);
            }
    }
    __syncthreads();
    float* stage = reinterpret_cast<float*>(smem);          // [128][72]
#pragma unroll
    for (int i = 0; i < 2; i++)
#pragma unroll
        for (int j = 0; j < 2; j++)
            wmma::store_matrix_sync(stage + (wm + i * 16) * K4_ALD + wn + j * 16,
                                    acc[i][j], K4_ALD, wmma::mem_row_major);
    __syncthreads();
#pragma unroll
    for (int k = 0; k < 8; k++) {
        int g = tid + k * 256;               // 2048 groups of 4 = 128 rows x 16
        int row = g >> 4, c4 = g & 15;
        float4 v = *reinterpret_cast<const float4*>(&stage[row * K4_ALD + c4 * 4]);
        __half2 p0 = __floats2half2_rn(v.x, v.y);
        __half2 p1 = __floats2half2_rn(v.z, v.w);
        uint2 o = make_uint2(*reinterpret_cast<uint32_t*>(&p0),
                             *reinterpret_cast<uint32_t*>(&p1));
        *reinterpret_cast<uint2*>(
            &g_ypre[((size_t)b * DM2 + d0 + row) * LSZ + l0 + c4 * 4]) = o;
    }
}

// ============================================================
// shared fp32-input conv body (gate half)
// ============================================================
__device__ __forceinline__ void dwconv_emit(const float* __restrict__ wDW,
                                            const float* __restrict__ bDW,
                                            int c, int b,
                                            float* __restrict__ out,
                                            float sm[66][72]) {
    int tid = threadIdx.x;
    float w[9];
#pragma unroll
    for (int i = 0; i < 9; i++) w[i] = wDW[c * 9 + i];
    float bb = bDW[c];
    float4* ob4 = reinterpret_cast<float4*>(out + ((size_t)b * DMODEL + c) * LSZ);
#pragma unroll
    for (int k = 0; k < 4; k++) {
        int g = tid + k * 256;
        int row = g >> 4, c0 = (g & 15) * 4;
        float o[4];
#pragma unroll
        for (int u = 0; u < 4; u++) {
            int cc = c0 + u;
            float acc = bb;
#pragma unroll
            for (int i = 0; i < 3; i++)
#pragma unroll
                for (int j = 0; j < 3; j++)
                    acc += w[i * 3 + j] * sm[row + i][3 + cc + j];
            o[u] = acc;
        }
        ob4[g] = make_float4(o[0], o[1], o[2], o[3]);
    }
}

// k4b ypre half: fp16 input plane, channels 0..511, L2-friendly order.
__global__ void k4b_ypre(const float* __restrict__ wDW,
                         const float* __restrict__ bDW,
                         float* __restrict__ out) {
    __shared__ __align__(16) float sm[66][72];
    int b = (BATCH - 1) - blockIdx.y;
    int c = (DM2 - 1) - blockIdx.x;
    int tid = threadIdx.x;
    const uint2* plane2 = reinterpret_cast<const uint2*>(
        g_ypre + ((size_t)b * DM2 + c) * LSZ);

    if (tid < 72) { sm[0][tid] = 0.f; sm[65][tid] = 0.f; }
    else if (tid < 136) { int r = tid - 72 + 1; sm[r][3] = 0.f; sm[r][68] = 0.f; }
#pragma unroll
    for (int k = 0; k < 4; k++) {
        int g = tid + k * 256;               // 1024 groups of 4 halves
        uint2 raw = plane2[g];
        __half2 p0 = *reinterpret_cast<__half2*>(&raw.x);
        __half2 p1 = *reinterpret_cast<__half2*>(&raw.y);
        float2 f0 = __half22float2(p0);
        float2 f1 = __half22float2(p1);
        int row = g >> 4, cq = g & 15;
        *reinterpret_cast<float4*>(&sm[row + 1][4 + cq * 4]) =
            make_float4(f0.x, f0.y, f1.x, f1.y);
    }
    __syncthreads();
    dwconv_emit(wDW, bDW, c, b, out, sm);
}

// k4b gate half: fp32 x input, channels 512..1023. Runs on side stream.
__global__ void k4b_gate(const float* __restrict__ x,
                         const float* __restrict__ wDW,
                         const float* __restrict__ bDW,
                         float* __restrict__ out) {
    __shared__ __align__(16) float sm[66][72];
    int b = blockIdx.y;
    int c = DM2 + blockIdx.x;
    int tid = threadIdx.x;
    const float4* plane4 = reinterpret_cast<const float4*>(
        x + ((size_t)b * DMODEL + c) * LSZ);

    if (tid < 72) { sm[0][tid] = 0.f; sm[65][tid] = 0.f; }
    else if (tid < 136) { int r = tid - 72 + 1; sm[r][3] = 0.f; sm[r][68] = 0.f; }
#pragma unroll
    for (int k = 0; k < 4; k++) {
        int g = tid + k * 256;
        int row = g >> 4, cq = g & 15;
        *reinterpret_cast<float4*>(&sm[row + 1][4 + cq * 4]) = plane4[g];
    }
    __syncthreads();
    dwconv_emit(wDW, bDW, c, b, out, sm);
}

// ============================================================
extern "C" void kernel_launch(void* const* d_in, const int* in_sizes, int n_in,
                              void* d_out, int out_size) {
    const float* x      = (const float*)d_in[0];
    const float* w_bcdt = (const float*)d_in[1];
    const float* b_bcdt = (const float*)d_in[2];
    const float* w_dw   = (const float*)d_in[3];
    const float* b_dw   = (const float*)d_in[4];
    const float* A      = (const float*)d_in[5];
    const float* coeffs = (const float*)d_in[6];
    const float* w_DW   = (const float*)d_in[7];
    const float* b_DW   = (const float*)d_in[8];

    float* y_out = (float*)d_out;                          // (16,1024,4096)
    float* h_out = y_out + (size_t)BATCH * DMODEL * LSZ;   // (16,512,64)

    cudaFuncSetAttribute(k1_wmma, cudaFuncAttributeMaxDynamicSharedMemorySize, K1_SMEM);
    cudaFuncSetAttribute(k3_wmma, cudaFuncAttributeMaxDynamicSharedMemorySize, K3_SMEM);
    cudaFuncSetAttribute(k4a_wmma, cudaFuncAttributeMaxDynamicSharedMemorySize, K4_SMEM);

    // ---- fork: gate conv (depends only on x) runs on side stream ----
    cudaEventRecord(g_si.evFork, 0);
    cudaStreamWaitEvent(g_si.side, g_si.evFork, 0);
    k4b_gate<<<dim3(DM2, BATCH), 256, 0, g_si.side>>>(x, w_DW, b_DW, y_out);
    cudaEventRecord(g_si.evJoin, g_si.side);

    // ---- main pipeline ----
    cudaMemsetAsync(h_out, 0, (size_t)BATCH * DM2 * SS * sizeof(float));
    k0_convert_w<<<8, 256>>>((const float4*)w_bcdt);
    k1_wmma<<<dim3(32, 16), 256, K1_SMEM>>>((const float4*)x, b_bcdt);
    k2_conv_softmax<<<dim3(64, 16), 256>>>(w_dw, b_dw, A, coeffs);
    k3_wmma<<<dim3(8, 4, 16), 256, K3_SMEM>>>((const float4*)x, h_out);
    k4a_wmma<<<dim3(64, 4, 16), 256, K4_SMEM>>>((const float4*)h_out, coeffs);
    k4b_ypre<<<dim3(DM2, BATCH), 256>>>(w_DW, b_DW, y_out);

    // ---- join ----
    cudaStreamWaitEvent(0, g_si.evJoin, 0);
}